// round 1
// baseline (speedup 1.0000x reference)
#include <cuda_runtime.h>
#include <math.h>
#include <stdint.h>

// ---------------------------------------------------------------------------
// Problem constants
// ---------------------------------------------------------------------------
// x: (B=4, C=64, T=256, Q=128) fp32.  D = 128 (C*KS), DKV = 256, H=4, Dk=Dv=64, CS=32
// Pass1 (intra): N1 = B*T = 1024 sequences, L1 = 127, Lf1 = 128, nc1 = 4
// Pass2 (inter): N2 = B*Q = 512  sequences, L2 = 255, Lf2 = 256, nc2 = 8

#define CDIV(a,b) (((a)+(b)-1)/(b))

constexpr int MAXTOK = 130560;     // max(1024*127, 512*255)
constexpr int ELEMS  = 4*64*256*128;

// ---------------------------------------------------------------------------
// Scratch arena (static device memory; no runtime allocation)
// ---------------------------------------------------------------------------
constexpr size_t OF_F   = 0;                              // f   : MAXTOK*128
constexpr size_t OF_Q   = OF_F   + (size_t)MAXTOK*128;    // q   : MAXTOK*256
constexpr size_t OF_K   = OF_Q   + (size_t)MAXTOK*256;
constexpr size_t OF_V   = OF_K   + (size_t)MAXTOK*256;
constexpr size_t OF_R   = OF_V   + (size_t)MAXTOK*256;
constexpr size_t OF_GK  = OF_R   + (size_t)MAXTOK*256;
constexpr size_t OF_O   = OF_GK  + (size_t)MAXTOK*256;
constexpr size_t OF_OG  = OF_O   + (size_t)MAXTOK*256;
constexpr size_t OF_T32 = OF_OG  + (size_t)MAXTOK*256;    // tmp : MAXTOK*32
constexpr size_t OF_G   = OF_T32 + (size_t)MAXTOK*32;     // g   : MAXTOK*128
constexpr size_t OF_D0  = OF_G   + (size_t)MAXTOK*128;    // d0  : MAXTOK*64
constexpr size_t OF_D1  = OF_D0  + (size_t)MAXTOK*64;
constexpr size_t OF_UN  = OF_D1  + (size_t)MAXTOK*64;     // un  : 8388608
constexpr size_t OF_Y4  = OF_UN  + (size_t)ELEMS;         // y4  : 8388608
constexpr size_t ARENA_TOTAL = OF_Y4 + (size_t)ELEMS;

__device__ float g_arena[ARENA_TOTAL];

// ---------------------------------------------------------------------------
// LayerNorm over channel dim C=64 at each (b,t,q), written in pass layout.
// pass 0: un[(b*256+t)*64 + c][128] indexed by q
// pass 1: un[(b*128+q)*64 + c][256] indexed by t
// ---------------------------------------------------------------------------
__global__ void ln_kernel(const float* __restrict__ x,
                          const float* __restrict__ gamma,
                          const float* __restrict__ beta,
                          float* __restrict__ un, int pass)
{
    int idx = blockIdx.x * blockDim.x + threadIdx.x;   // over B*T*Q = 131072
    if (idx >= 4*256*128) return;
    int q = idx & 127;
    int t = (idx >> 7) & 255;
    int b = idx >> 15;
    size_t base = ((size_t)b*64*256 + t)*128 + q;      // x[b][0][t][q]
    float sum = 0.f, sq = 0.f;
    #pragma unroll 8
    for (int c = 0; c < 64; c++) {
        float v = x[base + (size_t)c*32768];
        sum += v; sq += v*v;
    }
    float mu  = sum * (1.f/64.f);
    float var = sq  * (1.f/64.f) - mu*mu;
    float inv = rsqrtf(var + 1e-5f);
    #pragma unroll 8
    for (int c = 0; c < 64; c++) {
        float v = (x[base + (size_t)c*32768] - mu) * inv * gamma[c] + beta[c];
        size_t o;
        if (pass == 0) o = (((size_t)(b*256 + t))*64 + c)*128 + q;
        else           o = (((size_t)(b*128 + q))*64 + c)*256 + t;
        un[o] = v;
    }
}

// ---------------------------------------------------------------------------
// Unfold: f[n, l, 2c+k] = un[n, c, l+k]   (KS=2, stride 1)
// ---------------------------------------------------------------------------
__global__ void buildf_kernel(const float* __restrict__ un, float* __restrict__ f,
                              int Nn, int Lf, int L)
{
    size_t idx = (size_t)blockIdx.x * blockDim.x + threadIdx.x;
    size_t total = (size_t)Nn * 64 * L;
    if (idx >= total) return;
    int l = (int)(idx % L);
    int c = (int)((idx / L) % 64);
    int n = (int)(idx / ((size_t)L * 64));
    const float* up = un + ((size_t)n*64 + c)*Lf + l;
    float2 v = make_float2(up[0], up[1]);
    *reinterpret_cast<float2*>(f + ((size_t)n*L + l)*128 + 2*c) = v;
}

// ---------------------------------------------------------------------------
// SGEMM: C[M,N] = A[M,K] @ B  with B element (k,n) at B[k*brs + n*bcs + boff]
// BM=128, BN=64, BK=16, 256 threads, 8x4 register tile.
// epi: 0=none, 1=*0.125 (q-scale), 2=log_sigmoid(z)/32
// ---------------------------------------------------------------------------
__global__ void gemm_kernel(const float* __restrict__ A, const float* __restrict__ B,
                            float* __restrict__ C, int M, int N, int K,
                            int brs, int bcs, int boff, int epi)
{
    __shared__ float As[16][132];
    __shared__ float Bs[16][68];
    int m0 = blockIdx.x * 128;
    int n0 = blockIdx.y * 64;
    int tid = threadIdx.x;
    int rid = tid >> 4;
    int cid = tid & 15;
    float acc[8][4] = {};

    for (int k0 = 0; k0 < K; k0 += 16) {
        #pragma unroll
        for (int i = tid; i < 128*16; i += 256) {
            int kk = i & 15, mm = i >> 4;
            int m = m0 + mm;
            As[kk][mm] = (m < M) ? A[(size_t)m*K + k0 + kk] : 0.f;
        }
        #pragma unroll
        for (int i = tid; i < 64*16; i += 256) {
            int nn = i & 63, kk = i >> 6;
            int n = n0 + nn;
            Bs[kk][nn] = (n < N) ? B[(size_t)(k0+kk)*brs + (size_t)n*bcs + boff] : 0.f;
        }
        __syncthreads();
        #pragma unroll
        for (int kk = 0; kk < 16; kk++) {
            float4 a0 = *reinterpret_cast<const float4*>(&As[kk][rid*8]);
            float4 a1 = *reinterpret_cast<const float4*>(&As[kk][rid*8+4]);
            float4 b0 = *reinterpret_cast<const float4*>(&Bs[kk][cid*4]);
            float a[8] = {a0.x,a0.y,a0.z,a0.w,a1.x,a1.y,a1.z,a1.w};
            float b[4] = {b0.x,b0.y,b0.z,b0.w};
            #pragma unroll
            for (int i = 0; i < 8; i++)
                #pragma unroll
                for (int j = 0; j < 4; j++)
                    acc[i][j] += a[i]*b[j];
        }
        __syncthreads();
    }
    #pragma unroll
    for (int i = 0; i < 8; i++) {
        int m = m0 + rid*8 + i;
        if (m >= M) continue;
        #pragma unroll
        for (int j = 0; j < 4; j++) {
            int n = n0 + cid*4 + j;
            if (n >= N) continue;
            float v = acc[i][j];
            if (epi == 1) v *= 0.125f;
            else if (epi == 2) v = (fminf(v, 0.f) - log1pf(expf(-fabsf(v)))) * (1.f/32.f);
            C[(size_t)m*N + n] = v;
        }
    }
}

// ---------------------------------------------------------------------------
// Chunked GLA. One block per (sequence n, head h); carries S[64][64] in shared
// across chunks. CS=32.
// ---------------------------------------------------------------------------
__global__ void gla_kernel(const float* __restrict__ qb, const float* __restrict__ kb,
                           const float* __restrict__ vb, const float* __restrict__ gkb,
                           float* __restrict__ ob, int N, int L, int nc)
{
    int n = blockIdx.x >> 2;
    int h = blockIdx.x & 3;
    int tid = threadIdx.x;

    __shared__ float S[64][65];
    __shared__ float Qs[32][65];
    __shared__ float Ks[32][65];
    __shared__ float Vs[32][65];     // also used as gc scratch
    __shared__ float Amat[32][33];
    __shared__ float gl[64];

    for (int i = tid; i < 64*64; i += 256) S[i>>6][i&63] = 0.f;
    __syncthreads();

    for (int c = 0; c < nc; c++) {
        int lbase = c*32;
        // ---- load gk chunk into Vs (scratch for gc)
        for (int i = tid; i < 2048; i += 256) {
            int t = i >> 6, d = i & 63;
            int l = lbase + t;
            Vs[t][d] = (l < L) ? gkb[((size_t)(n*L + l))*256 + h*64 + d] : 0.f;
        }
        __syncthreads();
        // ---- cumsum along t (per d), record gl
        if (tid < 64) {
            float s = 0.f;
            #pragma unroll
            for (int t = 0; t < 32; t++) { s += Vs[t][tid]; Vs[t][tid] = s; }
            gl[tid] = s;
        }
        __syncthreads();
        // ---- q_i = q*exp(gc), k_i = k*exp(-gc)
        for (int i = tid; i < 2048; i += 256) {
            int t = i >> 6, d = i & 63;
            int l = lbase + t;
            float gc = Vs[t][d];
            float qv = 0.f, kv = 0.f;
            if (l < L) {
                size_t base = ((size_t)(n*L + l))*256 + h*64 + d;
                qv = qb[base] * expf(gc);
                kv = kb[base] * expf(-gc);
            }
            Qs[t][d] = qv;
            Ks[t][d] = kv;
        }
        __syncthreads();
        // ---- v chunk (overwrite scratch)
        for (int i = tid; i < 2048; i += 256) {
            int t = i >> 6, d = i & 63;
            int l = lbase + t;
            Vs[t][d] = (l < L) ? vb[((size_t)(n*L + l))*256 + h*64 + d] : 0.f;
        }
        __syncthreads();
        // ---- A[t][s] = q_i[t] . k_i[s], masked s<=t
        {
            int t  = tid >> 3;
            int s0 = (tid & 7) * 4;
            float acc[4] = {0.f,0.f,0.f,0.f};
            #pragma unroll 16
            for (int d = 0; d < 64; d++) {
                float qv = Qs[t][d];
                #pragma unroll
                for (int i = 0; i < 4; i++) acc[i] += qv * Ks[s0+i][d];
            }
            #pragma unroll
            for (int i = 0; i < 4; i++)
                Amat[t][s0+i] = (s0+i <= t) ? acc[i] : 0.f;
        }
        __syncthreads();
        // ---- o[t] = A[t,:] @ V + q_i[t] @ S   (old S)
        {
            int t   = tid >> 3;
            int dv0 = (tid & 7) * 8;
            float acc[8] = {};
            #pragma unroll 8
            for (int s = 0; s < 32; s++) {
                float a = Amat[t][s];
                #pragma unroll
                for (int j = 0; j < 8; j++) acc[j] += a * Vs[s][dv0+j];
            }
            #pragma unroll 8
            for (int dk = 0; dk < 64; dk++) {
                float qv = Qs[t][dk];
                #pragma unroll
                for (int j = 0; j < 8; j++) acc[j] += qv * S[dk][dv0+j];
            }
            int l = lbase + t;
            if (l < L) {
                size_t base = ((size_t)(n*L + l))*256 + h*64 + dv0;
                #pragma unroll
                for (int j = 0; j < 8; j++) ob[base + j] = acc[j];
            }
        }
        __syncthreads();
        // ---- S = exp(gl[dk]) * (S + k_i^T V)
        {
            int dk0 = (tid >> 4) * 4;
            int dv0 = (tid & 15) * 4;
            float acc[4][4] = {};
            #pragma unroll 8
            for (int s = 0; s < 32; s++) {
                float kk[4], vv[4];
                #pragma unroll
                for (int i = 0; i < 4; i++) kk[i] = Ks[s][dk0+i];
                #pragma unroll
                for (int j = 0; j < 4; j++) vv[j] = Vs[s][dv0+j];
                #pragma unroll
                for (int i = 0; i < 4; i++)
                    #pragma unroll
                    for (int j = 0; j < 4; j++)
                        acc[i][j] += kk[i]*vv[j];
            }
            #pragma unroll
            for (int i = 0; i < 4; i++) {
                float e = expf(gl[dk0+i]);
                #pragma unroll
                for (int j = 0; j < 4; j++)
                    S[dk0+i][dv0+j] = e * (S[dk0+i][dv0+j] + acc[i][j]);
            }
        }
        __syncthreads();
    }
}

// ---------------------------------------------------------------------------
// Per-head RMS norm over Dv=64, *gn, *silu(r).  One warp per (token, head).
// ---------------------------------------------------------------------------
__global__ void gate_kernel(const float* __restrict__ o, const float* __restrict__ r,
                            const float* __restrict__ gn, float* __restrict__ og,
                            int tokens)
{
    int item = blockIdx.x * 8 + (threadIdx.x >> 5);
    int lane = threadIdx.x & 31;
    if (item >= tokens*4) return;
    int m = item >> 2, h = item & 3;
    size_t base = (size_t)m*256 + h*64;
    float v0 = o[base + lane], v1 = o[base + lane + 32];
    float ss = v0*v0 + v1*v1;
    #pragma unroll
    for (int off = 16; off; off >>= 1) ss += __shfl_xor_sync(0xFFFFFFFFu, ss, off);
    float inv = rsqrtf(ss * (1.f/64.f) + 1e-5f);
    float r0 = r[base + lane], r1 = r[base + lane + 32];
    float s0 = r0 / (1.f + expf(-r0));
    float s1 = r1 / (1.f + expf(-r1));
    og[base + lane]      = v0 * inv * gn[h*64 + lane]      * s0;
    og[base + lane + 32] = v1 * inv * gn[h*64 + lane + 32] * s1;
}

// ---------------------------------------------------------------------------
// Deconv combine + residual.  d0/d1 are g @ w[:,:,0] and g @ w[:,:,1].
// pass 0: along Q (n=b*256+t, p=q, L=127); pass 1: along T (n=b*128+q, p=t, L=255)
// ---------------------------------------------------------------------------
__global__ void combine_kernel(const float* __restrict__ dd0, const float* __restrict__ dd1,
                               const float* __restrict__ ctb, const float* __restrict__ resid,
                               float* __restrict__ out, int pass)
{
    int idx = blockIdx.x * blockDim.x + threadIdx.x;
    if (idx >= ELEMS) return;
    int q = idx & 127;
    int t = (idx >> 7) & 255;
    int c = (idx >> 15) & 63;
    int b = idx >> 21;
    float acc = resid[idx] + ctb[c];
    if (pass == 0) {
        int n = b*256 + t;
        if (q < 127) acc += dd0[((size_t)n*127 + q    )*64 + c];
        if (q >= 1)  acc += dd1[((size_t)n*127 + q - 1)*64 + c];
    } else {
        int n = b*128 + q;
        if (t < 255) acc += dd0[((size_t)n*255 + t    )*64 + c];
        if (t >= 1)  acc += dd1[((size_t)n*255 + t - 1)*64 + c];
    }
    out[idx] = acc;
}

// ---------------------------------------------------------------------------
// Host side
// ---------------------------------------------------------------------------
static void run_pass(const float* input,
                     const float* gamma, const float* beta,
                     const float* Wq, const float* Wk, const float* Wv,
                     const float* Wg1, const float* Wg2, const float* Wr,
                     const float* gn, const float* Wo,
                     const float* ctw, const float* ctb,
                     const float* resid, float* out,
                     float* A, int pass)
{
    const int N   = pass == 0 ? 1024 : 512;
    const int L   = pass == 0 ? 127  : 255;
    const int Lf  = pass == 0 ? 128  : 256;
    const int nc  = pass == 0 ? 4    : 8;
    const int tok = N * L;

    float* f   = A + OF_F;
    float* q   = A + OF_Q;
    float* k   = A + OF_K;
    float* v   = A + OF_V;
    float* r   = A + OF_R;
    float* gk  = A + OF_GK;
    float* o   = A + OF_O;
    float* og  = A + OF_OG;
    float* t32 = A + OF_T32;
    float* g   = A + OF_G;
    float* d0  = A + OF_D0;
    float* d1  = A + OF_D1;
    float* un  = A + OF_UN;

    // 1. LayerNorm (channel dim) into pass layout
    ln_kernel<<<CDIV(4*256*128, 256), 256>>>(input, gamma, beta, un, pass);
    // 2. Unfold
    buildf_kernel<<<(unsigned)CDIV((size_t)N*64*L, 256), 256>>>(un, f, N, Lf, L);
    // 3. q/k/v/r projections (DKV=256)
    {
        dim3 gq(CDIV(tok,128), 4);
        gemm_kernel<<<gq, 256>>>(f, Wq, q, tok, 256, 128, 256, 1, 0, 1); // *1/sqrt(Dk)
        gemm_kernel<<<gq, 256>>>(f, Wk, k, tok, 256, 128, 256, 1, 0, 0);
        gemm_kernel<<<gq, 256>>>(f, Wv, v, tok, 256, 128, 256, 1, 0, 0);
        gemm_kernel<<<gq, 256>>>(f, Wr, r, tok, 256, 128, 256, 1, 0, 0);
    }
    // 4. gk = log_sigmoid(f @ Wg1 @ Wg2) / 32
    gemm_kernel<<<dim3(CDIV(tok,128), 1), 256>>>(f, Wg1, t32, tok, 32, 128, 32, 1, 0, 0);
    gemm_kernel<<<dim3(CDIV(tok,128), 4), 256>>>(t32, Wg2, gk, tok, 256, 32, 256, 1, 0, 2);
    // 5. Chunked GLA
    gla_kernel<<<N*4, 256>>>(q, k, v, gk, o, N, L, nc);
    // 6. RMS-norm + gn + silu(r) gate
    gate_kernel<<<CDIV(tok*4, 8), 256>>>(o, r, gn, og, tok);
    // 7. Output projection
    gemm_kernel<<<dim3(CDIV(tok,128), 2), 256>>>(og, Wo, g, tok, 128, 256, 128, 1, 0, 0);
    // 8. Deconv as two strided-B GEMMs (ct_w shape (128,64,2))
    gemm_kernel<<<dim3(CDIV(tok,128), 1), 256>>>(g, ctw, d0, tok, 64, 128, 128, 2, 0, 0);
    gemm_kernel<<<dim3(CDIV(tok,128), 1), 256>>>(g, ctw, d1, tok, 64, 128, 128, 2, 1, 0);
    // 9. Shift-combine + bias + residual
    combine_kernel<<<CDIV(ELEMS, 256), 256>>>(d0, d1, ctb, resid, out, pass);
}

extern "C" void kernel_launch(void* const* d_in, const int* in_sizes, int n_in,
                              void* d_out, int out_size)
{
    const float* x = (const float*)d_in[0];
    auto P = [&](int i) { return (const float*)d_in[i]; };

    float* arena = nullptr;
    cudaGetSymbolAddress((void**)&arena, g_arena);
    float* y4 = arena + OF_Y4;

    // Pass 1 (intra): along Q.  params d_in[2..13]
    run_pass(x,
             P(2), P(3), P(4), P(5), P(6), P(7), P(8), P(9), P(10), P(11), P(12), P(13),
             x, y4, arena, 0);

    // Pass 2 (inter): along T.  params d_in[14..25]
    run_pass(y4,
             P(14), P(15), P(16), P(17), P(18), P(19), P(20), P(21), P(22), P(23), P(24), P(25),
             y4, (float*)d_out, arena, 1);
}

// round 2
// speedup vs baseline: 1.3242x; 1.3242x over previous
#include <cuda_runtime.h>
#include <math.h>
#include <stdint.h>

#define CDIV(a,b) (((a)+(b)-1)/(b))

constexpr int MAXTOK = 130560;     // max(1024*127, 512*255)
constexpr int ELEMS  = 4*64*256*128;

// ---------------------------------------------------------------------------
// Scratch arena (static device memory; no runtime allocation)
// ---------------------------------------------------------------------------
constexpr size_t OF_F    = 0;                               // f    : MAXTOK*128
constexpr size_t OF_QKVR = OF_F    + (size_t)MAXTOK*128;    // qkvr : MAXTOK*1024
constexpr size_t OF_GK   = OF_QKVR + (size_t)MAXTOK*1024;   // gk   : MAXTOK*256
constexpr size_t OF_O    = OF_GK   + (size_t)MAXTOK*256;    // o    : MAXTOK*256
constexpr size_t OF_OG   = OF_O    + (size_t)MAXTOK*256;    // og   : MAXTOK*256
constexpr size_t OF_T32  = OF_OG   + (size_t)MAXTOK*256;    // t32  : MAXTOK*32
constexpr size_t OF_G    = OF_T32  + (size_t)MAXTOK*32;     // g    : MAXTOK*128
constexpr size_t OF_D01  = OF_G    + (size_t)MAXTOK*128;    // d01  : MAXTOK*128
constexpr size_t OF_UN   = OF_D01  + (size_t)MAXTOK*128;    // un   : ELEMS
constexpr size_t OF_Y4   = OF_UN   + (size_t)ELEMS;         // y4   : ELEMS
constexpr size_t OF_WP   = OF_Y4   + (size_t)ELEMS;         // wp   : 128*1024
constexpr size_t ARENA_TOTAL = OF_WP + (size_t)128*1024;

__device__ float g_arena[ARENA_TOTAL];

// ---------------------------------------------------------------------------
// Pack Wq*0.125 | Wk | Wv | Wr into wp[128][1024]
// ---------------------------------------------------------------------------
__global__ void pack_kernel(const float* __restrict__ Wq, const float* __restrict__ Wk,
                            const float* __restrict__ Wv, const float* __restrict__ Wr,
                            float* __restrict__ wp)
{
    int idx = blockIdx.x * 256 + threadIdx.x;          // 128*256 = 32768
    if (idx >= 128*256) return;
    int k = idx >> 8, nn = idx & 255;
    wp[k*1024 +       nn] = Wq[idx] * 0.125f;
    wp[k*1024 + 256 + nn] = Wk[idx];
    wp[k*1024 + 512 + nn] = Wv[idx];
    wp[k*1024 + 768 + nn] = Wr[idx];
}

// ---------------------------------------------------------------------------
// LayerNorm over channel dim C=64 at each (b,t,q), written in pass layout.
// pass 0: un[(b*256+t)*64 + c][128] indexed by q
// pass 1: un[(b*128+q)*64 + c][256] indexed by t
// ---------------------------------------------------------------------------
__global__ void ln_kernel(const float* __restrict__ x,
                          const float* __restrict__ gamma,
                          const float* __restrict__ beta,
                          float* __restrict__ un, int pass)
{
    int idx = blockIdx.x * blockDim.x + threadIdx.x;   // over B*T*Q = 131072
    if (idx >= 4*256*128) return;
    int q = idx & 127;
    int t = (idx >> 7) & 255;
    int b = idx >> 15;
    size_t base = ((size_t)b*64*256 + t)*128 + q;      // x[b][0][t][q]
    float sum = 0.f, sq = 0.f;
    #pragma unroll 8
    for (int c = 0; c < 64; c++) {
        float v = x[base + (size_t)c*32768];
        sum += v; sq += v*v;
    }
    float mu  = sum * (1.f/64.f);
    float var = sq  * (1.f/64.f) - mu*mu;
    float inv = rsqrtf(var + 1e-5f);
    #pragma unroll 8
    for (int c = 0; c < 64; c++) {
        float v = (x[base + (size_t)c*32768] - mu) * inv * gamma[c] + beta[c];
        size_t o;
        if (pass == 0) o = (((size_t)(b*256 + t))*64 + c)*128 + q;
        else           o = (((size_t)(b*128 + q))*64 + c)*256 + t;
        un[o] = v;
    }
}

// ---------------------------------------------------------------------------
// Unfold: f[n, l, 2c+k] = un[n, c, l+k]   (KS=2, stride 1)
// ---------------------------------------------------------------------------
__global__ void buildf_kernel(const float* __restrict__ un, float* __restrict__ f,
                              int Nn, int Lf, int L)
{
    size_t idx = (size_t)blockIdx.x * blockDim.x + threadIdx.x;
    size_t total = (size_t)Nn * 64 * L;
    if (idx >= total) return;
    int l = (int)(idx % L);
    int c = (int)((idx / L) % 64);
    int n = (int)(idx / ((size_t)L * 64));
    const float* up = un + ((size_t)n*64 + c)*Lf + l;
    float2 v = make_float2(up[0], up[1]);
    *reinterpret_cast<float2*>(f + ((size_t)n*L + l)*128 + 2*c) = v;
}

// ---------------------------------------------------------------------------
// SGEMM v2: C[M,N] = A[M,K] @ B[K,N], all row-major contiguous.
// 128x128 block, BK=16, 256 threads, 8x8 micro-tile, double-buffered smem.
// Requirements: M % 128 == 0, K % 16 == 0, N % 4 == 0.
// EPI: 0=none, 2=log_sigmoid(z)/32
// ---------------------------------------------------------------------------
template<int EPI>
__global__ void __launch_bounds__(256, 2)
gemm2_kernel(const float* __restrict__ A, const float* __restrict__ B,
             float* __restrict__ C, int M, int N, int K)
{
    __shared__ float As[2][16][132];
    __shared__ float Bs[2][16][132];
    const int tid = threadIdx.x;
    const int m0 = blockIdx.x * 128;
    const int n0 = blockIdx.y * 128;
    const int rid = tid >> 4;
    const int cid = tid & 15;

    const int ar0 = tid >> 2;            // 0..63
    const int ar1 = ar0 + 64;            // 64..127
    const int ac0 = (tid & 3) * 4;       // 0,4,8,12
    const int bk0 = tid >> 5;            // 0..7
    const int bk1 = bk0 + 8;             // 8..15
    const int bn0 = (tid & 31) * 4;      // 0..124
    const bool bok = (n0 + bn0) < N;

    float4 va0, va1, vb0, vb1;
    const float4 z4 = make_float4(0.f, 0.f, 0.f, 0.f);

    // prologue: load tile k0=0 into stage 0
    va0 = *reinterpret_cast<const float4*>(&A[(size_t)(m0 + ar0)*K + ac0]);
    va1 = *reinterpret_cast<const float4*>(&A[(size_t)(m0 + ar1)*K + ac0]);
    vb0 = bok ? *reinterpret_cast<const float4*>(&B[(size_t)bk0*N + n0 + bn0]) : z4;
    vb1 = bok ? *reinterpret_cast<const float4*>(&B[(size_t)bk1*N + n0 + bn0]) : z4;
    As[0][ac0+0][ar0] = va0.x; As[0][ac0+1][ar0] = va0.y;
    As[0][ac0+2][ar0] = va0.z; As[0][ac0+3][ar0] = va0.w;
    As[0][ac0+0][ar1] = va1.x; As[0][ac0+1][ar1] = va1.y;
    As[0][ac0+2][ar1] = va1.z; As[0][ac0+3][ar1] = va1.w;
    *reinterpret_cast<float4*>(&Bs[0][bk0][bn0]) = vb0;
    *reinterpret_cast<float4*>(&Bs[0][bk1][bn0]) = vb1;
    __syncthreads();

    float acc[8][8];
    #pragma unroll
    for (int i = 0; i < 8; i++)
        #pragma unroll
        for (int j = 0; j < 8; j++) acc[i][j] = 0.f;

    int buf = 0;
    for (int k0 = 0; k0 < K; k0 += 16) {
        const bool nxt = (k0 + 16) < K;
        if (nxt) {
            const int kn = k0 + 16;
            va0 = *reinterpret_cast<const float4*>(&A[(size_t)(m0 + ar0)*K + kn + ac0]);
            va1 = *reinterpret_cast<const float4*>(&A[(size_t)(m0 + ar1)*K + kn + ac0]);
            vb0 = bok ? *reinterpret_cast<const float4*>(&B[(size_t)(kn + bk0)*N + n0 + bn0]) : z4;
            vb1 = bok ? *reinterpret_cast<const float4*>(&B[(size_t)(kn + bk1)*N + n0 + bn0]) : z4;
        }
        #pragma unroll
        for (int kk = 0; kk < 16; kk++) {
            float4 a0 = *reinterpret_cast<const float4*>(&As[buf][kk][rid*8]);
            float4 a1 = *reinterpret_cast<const float4*>(&As[buf][kk][rid*8+4]);
            float4 b0 = *reinterpret_cast<const float4*>(&Bs[buf][kk][cid*8]);
            float4 b1 = *reinterpret_cast<const float4*>(&Bs[buf][kk][cid*8+4]);
            float a[8] = {a0.x,a0.y,a0.z,a0.w,a1.x,a1.y,a1.z,a1.w};
            float b[8] = {b0.x,b0.y,b0.z,b0.w,b1.x,b1.y,b1.z,b1.w};
            #pragma unroll
            for (int i = 0; i < 8; i++)
                #pragma unroll
                for (int j = 0; j < 8; j++)
                    acc[i][j] = fmaf(a[i], b[j], acc[i][j]);
        }
        if (nxt) {
            const int nb = buf ^ 1;
            As[nb][ac0+0][ar0] = va0.x; As[nb][ac0+1][ar0] = va0.y;
            As[nb][ac0+2][ar0] = va0.z; As[nb][ac0+3][ar0] = va0.w;
            As[nb][ac0+0][ar1] = va1.x; As[nb][ac0+1][ar1] = va1.y;
            As[nb][ac0+2][ar1] = va1.z; As[nb][ac0+3][ar1] = va1.w;
            *reinterpret_cast<float4*>(&Bs[nb][bk0][bn0]) = vb0;
            *reinterpret_cast<float4*>(&Bs[nb][bk1][bn0]) = vb1;
        }
        __syncthreads();
        buf ^= 1;
    }

    // epilogue
    #pragma unroll
    for (int i = 0; i < 8; i++) {
        size_t m = (size_t)(m0 + rid*8 + i);
        float* crow = C + m * (size_t)N;
        #pragma unroll
        for (int j4 = 0; j4 < 2; j4++) {
            int n = n0 + cid*8 + j4*4;
            if (n < N) {
                float4 v;
                float* s = &acc[i][j4*4];
                if (EPI == 2) {
                    #pragma unroll
                    for (int u = 0; u < 4; u++) {
                        float z = s[u];
                        s[u] = (fminf(z, 0.f) - log1pf(__expf(-fabsf(z)))) * (1.f/32.f);
                    }
                }
                v.x = s[0]; v.y = s[1]; v.z = s[2]; v.w = s[3];
                *reinterpret_cast<float4*>(&crow[n]) = v;
            }
        }
    }
}

// ---------------------------------------------------------------------------
// Chunked GLA v2. One block per (sequence n, head h). S carried in smem.
// q/k/v read from fused qkvr buffer (row stride 1024; offsets 0/256/512).
// Exactly 48KB static smem: 5 stride-64 arrays with per-array swizzle.
// ---------------------------------------------------------------------------
__device__ __forceinline__ int swzQ(int t, int d) { return (d + ((t & 3)  << 2)) & 63; }
__device__ __forceinline__ int swzK(int s, int d) { return (d + (s & 28)) & 63; }

__global__ void __launch_bounds__(256)
gla_kernel(const float* __restrict__ qkvr, const float* __restrict__ gkb,
           float* __restrict__ ob, int Nseq, int L, int nc)
{
    const int n   = blockIdx.x >> 2;
    const int h   = blockIdx.x & 3;
    const int tid = threadIdx.x;

    __shared__ float S[64][64];
    __shared__ float Qs[32][64];
    __shared__ float Ks[32][64];
    __shared__ float Vs[32][64];
    __shared__ float U[32][64];      // Gs (gate cumsum), then Amat

    for (int i = tid; i < 64*64; i += 256) (&S[0][0])[i] = 0.f;
    __syncthreads();

    const int glk0 = (tid >> 4) * 4;     // dk0 for S-update / gl
    float glr[4];

    for (int c = 0; c < nc; c++) {
        const int lbase = c * 32;

        // ---- load gk chunk into U
        #pragma unroll
        for (int r = 0; r < 2; r++) {
            int i  = tid + r*256;
            int t  = i >> 4, d4 = (i & 15) * 4;
            int l  = lbase + t;
            float4 gv = make_float4(0.f, 0.f, 0.f, 0.f);
            if (l < L)
                gv = *reinterpret_cast<const float4*>(&gkb[((size_t)(n*L + l))*256 + h*64 + d4]);
            *reinterpret_cast<float4*>(&U[t][d4]) = gv;
        }
        __syncthreads();
        // ---- cumsum along t (per d)
        if (tid < 64) {
            float s = 0.f;
            #pragma unroll
            for (int t = 0; t < 32; t++) { s += U[t][tid]; U[t][tid] = s; }
        }
        __syncthreads();
        // ---- load q,k (scaled by exp(+-gc)) and v
        #pragma unroll
        for (int r = 0; r < 2; r++) {
            int i  = tid + r*256;
            int t  = i >> 4, d4 = (i & 15) * 4;
            int l  = lbase + t;
            float4 qv = make_float4(0,0,0,0), kv = qv, vv = qv;
            if (l < L) {
                size_t base = ((size_t)(n*L + l))*1024 + h*64 + d4;
                qv = *reinterpret_cast<const float4*>(&qkvr[base]);
                kv = *reinterpret_cast<const float4*>(&qkvr[base + 256]);
                vv = *reinterpret_cast<const float4*>(&qkvr[base + 512]);
                float4 g = *reinterpret_cast<const float4*>(&U[t][d4]);
                qv.x *= __expf(g.x);  qv.y *= __expf(g.y);
                qv.z *= __expf(g.z);  qv.w *= __expf(g.w);
                kv.x *= __expf(-g.x); kv.y *= __expf(-g.y);
                kv.z *= __expf(-g.z); kv.w *= __expf(-g.w);
            }
            *reinterpret_cast<float4*>(&Qs[t][swzQ(t, d4)]) = qv;
            *reinterpret_cast<float4*>(&Ks[t][swzK(t, d4)]) = kv;
            *reinterpret_cast<float4*>(&Vs[t][d4]) = vv;
        }
        // gl (chunk-final cumsum) into registers before U is reused for Amat
        #pragma unroll
        for (int i = 0; i < 4; i++) glr[i] = U[31][glk0 + i];
        __syncthreads();

        // ---- A[t][s] = q_i[t].k_i[s], masked s<=t, into U
        {
            int t  = tid >> 3;
            int s0 = (tid & 7) * 4;
            float a[4] = {0.f, 0.f, 0.f, 0.f};
            #pragma unroll
            for (int d = 0; d < 64; d += 4) {
                float4 q4 = *reinterpret_cast<const float4*>(&Qs[t][swzQ(t, d)]);
                #pragma unroll
                for (int i = 0; i < 4; i++) {
                    float4 k4 = *reinterpret_cast<const float4*>(&Ks[s0+i][swzK(s0+i, d)]);
                    a[i] += q4.x*k4.x + q4.y*k4.y + q4.z*k4.z + q4.w*k4.w;
                }
            }
            #pragma unroll
            for (int i = 0; i < 4; i++)
                U[t][s0+i] = (s0 + i <= t) ? a[i] : 0.f;
        }
        __syncthreads();

        // ---- o[t] = A[t,:] @ V + q_i[t] @ S (old S)
        {
            int t   = tid >> 3;
            int dv0 = (tid & 7) * 8;
            float acc[8] = {};
            #pragma unroll 8
            for (int s = 0; s < 32; s++) {
                float a = U[t][s];
                float4 v0 = *reinterpret_cast<const float4*>(&Vs[s][dv0]);
                float4 v1 = *reinterpret_cast<const float4*>(&Vs[s][dv0+4]);
                acc[0] += a*v0.x; acc[1] += a*v0.y; acc[2] += a*v0.z; acc[3] += a*v0.w;
                acc[4] += a*v1.x; acc[5] += a*v1.y; acc[6] += a*v1.z; acc[7] += a*v1.w;
            }
            #pragma unroll 8
            for (int dk = 0; dk < 64; dk++) {
                float qv = Qs[t][swzQ(t, dk)];
                float4 s0v = *reinterpret_cast<const float4*>(&S[dk][dv0]);
                float4 s1v = *reinterpret_cast<const float4*>(&S[dk][dv0+4]);
                acc[0] += qv*s0v.x; acc[1] += qv*s0v.y; acc[2] += qv*s0v.z; acc[3] += qv*s0v.w;
                acc[4] += qv*s1v.x; acc[5] += qv*s1v.y; acc[6] += qv*s1v.z; acc[7] += qv*s1v.w;
            }
            int l = lbase + t;
            if (l < L) {
                float* op = ob + ((size_t)(n*L + l))*256 + h*64 + dv0;
                *reinterpret_cast<float4*>(op)     = make_float4(acc[0],acc[1],acc[2],acc[3]);
                *reinterpret_cast<float4*>(op + 4) = make_float4(acc[4],acc[5],acc[6],acc[7]);
            }
        }
        __syncthreads();

        // ---- S = exp(gl[dk]) * (S + k_i^T V)
        {
            int dk0 = glk0;
            int dv0 = (tid & 15) * 4;
            float acc[4][4] = {};
            #pragma unroll 8
            for (int s = 0; s < 32; s++) {
                float4 k4 = *reinterpret_cast<const float4*>(&Ks[s][swzK(s, dk0)]);
                float4 v4 = *reinterpret_cast<const float4*>(&Vs[s][dv0]);
                float kk[4] = {k4.x, k4.y, k4.z, k4.w};
                float vv[4] = {v4.x, v4.y, v4.z, v4.w};
                #pragma unroll
                for (int i = 0; i < 4; i++)
                    #pragma unroll
                    for (int j = 0; j < 4; j++)
                        acc[i][j] += kk[i]*vv[j];
            }
            #pragma unroll
            for (int i = 0; i < 4; i++) {
                float e = __expf(glr[i]);
                float4 sv = *reinterpret_cast<float4*>(&S[dk0+i][dv0]);
                sv.x = e*(sv.x + acc[i][0]);
                sv.y = e*(sv.y + acc[i][1]);
                sv.z = e*(sv.z + acc[i][2]);
                sv.w = e*(sv.w + acc[i][3]);
                *reinterpret_cast<float4*>(&S[dk0+i][dv0]) = sv;
            }
        }
        __syncthreads();
    }
}

// ---------------------------------------------------------------------------
// Per-head RMS norm over Dv=64, *gn, *silu(r).  One warp per (token, head).
// r read from fused qkvr (offset 768, row stride 1024).
// ---------------------------------------------------------------------------
__global__ void gate_kernel(const float* __restrict__ o, const float* __restrict__ qkvr,
                            const float* __restrict__ gn, float* __restrict__ og,
                            int tokens)
{
    int item = blockIdx.x * 8 + (threadIdx.x >> 5);
    int lane = threadIdx.x & 31;
    if (item >= tokens*4) return;
    int m = item >> 2, h = item & 3;
    size_t ob_ = (size_t)m*256  + h*64;
    size_t rb_ = (size_t)m*1024 + 768 + h*64;
    float v0 = o[ob_ + lane], v1 = o[ob_ + lane + 32];
    float ss = v0*v0 + v1*v1;
    #pragma unroll
    for (int off = 16; off; off >>= 1) ss += __shfl_xor_sync(0xFFFFFFFFu, ss, off);
    float inv = rsqrtf(ss * (1.f/64.f) + 1e-5f);
    float r0 = qkvr[rb_ + lane], r1 = qkvr[rb_ + lane + 32];
    float s0 = r0 / (1.f + __expf(-r0));
    float s1 = r1 / (1.f + __expf(-r1));
    og[ob_ + lane]      = v0 * inv * gn[h*64 + lane]      * s0;
    og[ob_ + lane + 32] = v1 * inv * gn[h*64 + lane + 32] * s1;
}

// ---------------------------------------------------------------------------
// Deconv combine + residual. d01[m][2c+j] holds g @ ctw (interleaved taps).
// pass 0: along Q (n=b*256+t, p=q, L=127); pass 1: along T (n=b*128+q, L=255)
// ---------------------------------------------------------------------------
__global__ void combine_kernel(const float* __restrict__ d01,
                               const float* __restrict__ ctb, const float* __restrict__ resid,
                               float* __restrict__ out, int pass)
{
    int idx = blockIdx.x * blockDim.x + threadIdx.x;
    if (idx >= ELEMS) return;
    int q = idx & 127;
    int t = (idx >> 7) & 255;
    int c = (idx >> 15) & 63;
    int b = idx >> 21;
    float acc = resid[idx] + ctb[c];
    if (pass == 0) {
        int n = b*256 + t;
        if (q < 127) acc += d01[((size_t)n*127 + q    )*128 + 2*c];
        if (q >= 1)  acc += d01[((size_t)n*127 + q - 1)*128 + 2*c + 1];
    } else {
        int n = b*128 + q;
        if (t < 255) acc += d01[((size_t)n*255 + t    )*128 + 2*c];
        if (t >= 1)  acc += d01[((size_t)n*255 + t - 1)*128 + 2*c + 1];
    }
    out[idx] = acc;
}

// ---------------------------------------------------------------------------
// Host side
// ---------------------------------------------------------------------------
static void run_pass(const float* input,
                     const float* gamma, const float* beta,
                     const float* Wq, const float* Wk, const float* Wv,
                     const float* Wg1, const float* Wg2, const float* Wr,
                     const float* gn, const float* Wo,
                     const float* ctw, const float* ctb,
                     const float* resid, float* out,
                     float* A, int pass)
{
    const int N   = pass == 0 ? 1024 : 512;
    const int L   = pass == 0 ? 127  : 255;
    const int Lf  = pass == 0 ? 128  : 256;
    const int nc  = pass == 0 ? 4    : 8;
    const int tok = N * L;                 // multiple of 128 in both passes

    float* f    = A + OF_F;
    float* qkvr = A + OF_QKVR;
    float* gk   = A + OF_GK;
    float* o    = A + OF_O;
    float* og   = A + OF_OG;
    float* t32  = A + OF_T32;
    float* g    = A + OF_G;
    float* d01  = A + OF_D01;
    float* un   = A + OF_UN;
    float* wp   = A + OF_WP;

    // 0. pack q/k/v/r weights (q scale folded in)
    pack_kernel<<<128, 256>>>(Wq, Wk, Wv, Wr, wp);
    // 1. LayerNorm (channel dim) into pass layout
    ln_kernel<<<CDIV(4*256*128, 256), 256>>>(input, gamma, beta, un, pass);
    // 2. Unfold
    buildf_kernel<<<(unsigned)CDIV((size_t)N*64*L, 256), 256>>>(un, f, N, Lf, L);
    // 3. fused q|k|v|r projection
    gemm2_kernel<0><<<dim3(tok/128, 8), 256>>>(f, wp, qkvr, tok, 1024, 128);
    // 4. gk = log_sigmoid(f @ Wg1 @ Wg2) / 32
    gemm2_kernel<0><<<dim3(tok/128, 1), 256>>>(f, Wg1, t32, tok, 32, 128);
    gemm2_kernel<2><<<dim3(tok/128, 2), 256>>>(t32, Wg2, gk, tok, 256, 32);
    // 5. Chunked GLA
    gla_kernel<<<N*4, 256>>>(qkvr, gk, o, N, L, nc);
    // 6. RMS-norm + gn + silu(r) gate
    gate_kernel<<<CDIV(tok*4, 8), 256>>>(o, qkvr, gn, og, tok);
    // 7. Output projection
    gemm2_kernel<0><<<dim3(tok/128, 1), 256>>>(og, Wo, g, tok, 128, 256);
    // 8. Deconv: one contiguous GEMM with interleaved taps (ctw viewed as [128,128])
    gemm2_kernel<0><<<dim3(tok/128, 1), 256>>>(g, ctw, d01, tok, 128, 128);
    // 9. Shift-combine + bias + residual
    combine_kernel<<<CDIV(ELEMS, 256), 256>>>(d01, ctb, resid, out, pass);
}

extern "C" void kernel_launch(void* const* d_in, const int* in_sizes, int n_in,
                              void* d_out, int out_size)
{
    const float* x = (const float*)d_in[0];
    auto P = [&](int i) { return (const float*)d_in[i]; };

    float* arena = nullptr;
    cudaGetSymbolAddress((void**)&arena, g_arena);
    float* y4 = arena + OF_Y4;

    // Pass 1 (intra): along Q.  params d_in[2..13]
    run_pass(x,
             P(2), P(3), P(4), P(5), P(6), P(7), P(8), P(9), P(10), P(11), P(12), P(13),
             x, y4, arena, 0);

    // Pass 2 (inter): along T.  params d_in[14..25]
    run_pass(y4,
             P(14), P(15), P(16), P(17), P(18), P(19), P(20), P(21), P(22), P(23), P(24), P(25),
             y4, (float*)d_out, arena, 1);
}

// round 3
// speedup vs baseline: 1.5399x; 1.1629x over previous
#include <cuda_runtime.h>
#include <math.h>
#include <stdint.h>

#define CDIV(a,b) (((a)+(b)-1)/(b))

typedef unsigned long long ull;

// ---- packed f32x2 helpers (sm_103a FFMA2 path) ------------------------------
__device__ __forceinline__ ull pk2(float x) {
    ull r; asm("mov.b64 %0, {%1, %1};" : "=l"(r) : "f"(x)); return r;
}
__device__ __forceinline__ void ffma2(ull& c, ull a, ull b) {
    asm("fma.rn.f32x2 %0, %1, %2, %0;" : "+l"(c) : "l"(a), "l"(b));
}
__device__ __forceinline__ float2 upk(ull v) {
    float2 f; asm("mov.b64 {%0, %1}, %2;" : "=f"(f.x), "=f"(f.y) : "l"(v)); return f;
}

constexpr int MAXTOK = 130560;     // max(1024*127, 512*255)
constexpr int ELEMS  = 4*64*256*128;

// ---------------------------------------------------------------------------
// Scratch arena (static device memory; no runtime allocation)
// ---------------------------------------------------------------------------
constexpr size_t OF_F    = 0;                               // f    : MAXTOK*128
constexpr size_t OF_QKVR = OF_F    + (size_t)MAXTOK*128;    // qkvr : MAXTOK*1024
constexpr size_t OF_GK   = OF_QKVR + (size_t)MAXTOK*1024;   // gk   : MAXTOK*256
constexpr size_t OF_OG   = OF_GK   + (size_t)MAXTOK*256;    // og   : MAXTOK*256
constexpr size_t OF_T32  = OF_OG   + (size_t)MAXTOK*256;    // t32  : MAXTOK*32
constexpr size_t OF_D01  = OF_T32  + (size_t)MAXTOK*32;     // d01  : MAXTOK*128
constexpr size_t OF_UN   = OF_D01  + (size_t)MAXTOK*128;    // un   : ELEMS
constexpr size_t OF_Y4   = OF_UN   + (size_t)ELEMS;         // y4   : ELEMS
constexpr size_t OF_WP   = OF_Y4   + (size_t)ELEMS;         // wp   : 128*1024
constexpr size_t OF_WF   = OF_WP   + (size_t)128*1024;      // wf   : 256*128
constexpr size_t ARENA_TOTAL = OF_WF + (size_t)256*128;

__device__ __align__(128) float g_arena[ARENA_TOTAL];

// ---------------------------------------------------------------------------
// Pack Wq*0.125 | Wk | Wv | Wr into wp[128][1024]
// ---------------------------------------------------------------------------
__global__ void pack_kernel(const float* __restrict__ Wq, const float* __restrict__ Wk,
                            const float* __restrict__ Wv, const float* __restrict__ Wr,
                            float* __restrict__ wp)
{
    int idx = blockIdx.x * 256 + threadIdx.x;          // 128*256 = 32768
    if (idx >= 128*256) return;
    int k = idx >> 8, nn = idx & 255;
    wp[k*1024 +       nn] = Wq[idx] * 0.125f;
    wp[k*1024 + 256 + nn] = Wk[idx];
    wp[k*1024 + 512 + nn] = Wv[idx];
    wp[k*1024 + 768 + nn] = Wr[idx];
}

// ---------------------------------------------------------------------------
// LayerNorm over channel dim C=64 at each (b,t,q), written in pass layout.
// ---------------------------------------------------------------------------
__global__ void ln_kernel(const float* __restrict__ x,
                          const float* __restrict__ gamma,
                          const float* __restrict__ beta,
                          float* __restrict__ un, int pass)
{
    int idx = blockIdx.x * blockDim.x + threadIdx.x;   // over B*T*Q = 131072
    if (idx >= 4*256*128) return;
    int q = idx & 127;
    int t = (idx >> 7) & 255;
    int b = idx >> 15;
    size_t base = ((size_t)b*64*256 + t)*128 + q;      // x[b][0][t][q]
    float sum = 0.f, sq = 0.f;
    #pragma unroll 8
    for (int c = 0; c < 64; c++) {
        float v = x[base + (size_t)c*32768];
        sum += v; sq += v*v;
    }
    float mu  = sum * (1.f/64.f);
    float var = sq  * (1.f/64.f) - mu*mu;
    float inv = rsqrtf(var + 1e-5f);
    #pragma unroll 8
    for (int c = 0; c < 64; c++) {
        float v = (x[base + (size_t)c*32768] - mu) * inv * gamma[c] + beta[c];
        size_t o;
        if (pass == 0) o = (((size_t)(b*256 + t))*64 + c)*128 + q;
        else           o = (((size_t)(b*128 + q))*64 + c)*256 + t;
        un[o] = v;
    }
}

// ---------------------------------------------------------------------------
// Unfold: f[n, l, 2c+k] = un[n, c, l+k]   (KS=2, stride 1)
// ---------------------------------------------------------------------------
__global__ void buildf_kernel(const float* __restrict__ un, float* __restrict__ f,
                              int Nn, int Lf, int L)
{
    size_t idx = (size_t)blockIdx.x * blockDim.x + threadIdx.x;
    size_t total = (size_t)Nn * 64 * L;
    if (idx >= total) return;
    int l = (int)(idx % L);
    int c = (int)((idx / L) % 64);
    int n = (int)(idx / ((size_t)L * 64));
    const float* up = un + ((size_t)n*64 + c)*Lf + l;
    float2 v = make_float2(up[0], up[1]);
    *reinterpret_cast<float2*>(f + ((size_t)n*L + l)*128 + 2*c) = v;
}

// ---------------------------------------------------------------------------
// SGEMM v3: C[M,N] = A[M,K] @ B[K,N], row-major. FFMA2 inner loop.
// 128xBN block, BK=16, 256 threads, 8x(BN/16) micro-tile, double-buffered.
// Requirements: M%128==0, K%16==0, N%BN==0 (exact tiles, no masking).
// EPI: 0=none, 2=log_sigmoid(z)/32
// ---------------------------------------------------------------------------
template<int EPI, int BN>
__global__ void __launch_bounds__(256, 2)
gemm2_kernel(const float* __restrict__ A, const float* __restrict__ B,
             float* __restrict__ C, int M, int N, int K)
{
    constexpr int TN  = BN / 16;   // 8 or 2 cols per thread
    constexpr int TN2 = TN / 2;    // packed accumulators per row
    __shared__ __align__(16) float As[2][16][132];
    __shared__ __align__(16) float Bs[2][16][BN + 4];

    const int tid = threadIdx.x;
    const int m0  = blockIdx.x * 128;
    const int n0  = blockIdx.y * BN;
    const int rid = tid >> 4;
    const int cid = tid & 15;

    const int ar0 = tid >> 2;            // 0..63
    const int ar1 = ar0 + 64;
    const int ac0 = (tid & 3) * 4;       // 0,4,8,12
    const int bkk = tid >> 4;            // 0..15
    const int bnn = (tid & 15) * TN;

    const float* Ap0 = A + (size_t)(m0 + ar0)*K + ac0;
    const float* Ap1 = A + (size_t)(m0 + ar1)*K + ac0;
    const float* Bp  = B + (size_t)bkk*N + n0 + bnn;

    float4 va0, va1, vb0, vb1; float2 vb2;

    // prologue -> stage 0
    va0 = *reinterpret_cast<const float4*>(Ap0);
    va1 = *reinterpret_cast<const float4*>(Ap1);
    if constexpr (TN == 8) {
        vb0 = *reinterpret_cast<const float4*>(Bp);
        vb1 = *reinterpret_cast<const float4*>(Bp + 4);
    } else {
        vb2 = *reinterpret_cast<const float2*>(Bp);
    }
    As[0][ac0+0][ar0] = va0.x; As[0][ac0+1][ar0] = va0.y;
    As[0][ac0+2][ar0] = va0.z; As[0][ac0+3][ar0] = va0.w;
    As[0][ac0+0][ar1] = va1.x; As[0][ac0+1][ar1] = va1.y;
    As[0][ac0+2][ar1] = va1.z; As[0][ac0+3][ar1] = va1.w;
    if constexpr (TN == 8) {
        *reinterpret_cast<float4*>(&Bs[0][bkk][bnn]) = vb0;
        *reinterpret_cast<float4*>(&Bs[0][bkk][bnn + 4]) = vb1;
    } else {
        *reinterpret_cast<float2*>(&Bs[0][bkk][bnn]) = vb2;
    }
    __syncthreads();

    ull acc[8][TN2];
    #pragma unroll
    for (int i = 0; i < 8; i++)
        #pragma unroll
        for (int j = 0; j < TN2; j++) acc[i][j] = 0ull;

    int buf = 0;
    for (int k0 = 0; k0 < K; k0 += 16) {
        const bool nxt = (k0 + 16) < K;
        if (nxt) {
            const int kn = k0 + 16;
            va0 = *reinterpret_cast<const float4*>(Ap0 + kn);
            va1 = *reinterpret_cast<const float4*>(Ap1 + kn);
            if constexpr (TN == 8) {
                vb0 = *reinterpret_cast<const float4*>(Bp + (size_t)kn*N);
                vb1 = *reinterpret_cast<const float4*>(Bp + (size_t)kn*N + 4);
            } else {
                vb2 = *reinterpret_cast<const float2*>(Bp + (size_t)kn*N);
            }
        }
        #pragma unroll
        for (int kk = 0; kk < 16; kk++) {
            float4 a0 = *reinterpret_cast<const float4*>(&As[buf][kk][rid*8]);
            float4 a1 = *reinterpret_cast<const float4*>(&As[buf][kk][rid*8+4]);
            float av[8] = {a0.x,a0.y,a0.z,a0.w,a1.x,a1.y,a1.z,a1.w};
            ull ap[8];
            #pragma unroll
            for (int i = 0; i < 8; i++) ap[i] = pk2(av[i]);
            ull bp[TN2];
            if constexpr (TN == 8) {
                ulonglong2 b01 = *reinterpret_cast<const ulonglong2*>(&Bs[buf][kk][cid*8]);
                ulonglong2 b23 = *reinterpret_cast<const ulonglong2*>(&Bs[buf][kk][cid*8 + 4]);
                bp[0] = b01.x; bp[1] = b01.y; bp[2] = b23.x; bp[3] = b23.y;
            } else {
                bp[0] = *reinterpret_cast<const ull*>(&Bs[buf][kk][cid*2]);
            }
            #pragma unroll
            for (int i = 0; i < 8; i++)
                #pragma unroll
                for (int j = 0; j < TN2; j++)
                    ffma2(acc[i][j], ap[i], bp[j]);
        }
        if (nxt) {
            const int nb = buf ^ 1;
            As[nb][ac0+0][ar0] = va0.x; As[nb][ac0+1][ar0] = va0.y;
            As[nb][ac0+2][ar0] = va0.z; As[nb][ac0+3][ar0] = va0.w;
            As[nb][ac0+0][ar1] = va1.x; As[nb][ac0+1][ar1] = va1.y;
            As[nb][ac0+2][ar1] = va1.z; As[nb][ac0+3][ar1] = va1.w;
            if constexpr (TN == 8) {
                *reinterpret_cast<float4*>(&Bs[nb][bkk][bnn]) = vb0;
                *reinterpret_cast<float4*>(&Bs[nb][bkk][bnn + 4]) = vb1;
            } else {
                *reinterpret_cast<float2*>(&Bs[nb][bkk][bnn]) = vb2;
            }
        }
        __syncthreads();
        buf ^= 1;
    }

    // epilogue
    #pragma unroll
    for (int i = 0; i < 8; i++) {
        float out[TN];
        #pragma unroll
        for (int j = 0; j < TN2; j++) {
            float2 f = upk(acc[i][j]);
            out[2*j] = f.x; out[2*j+1] = f.y;
        }
        if (EPI == 2) {
            #pragma unroll
            for (int u = 0; u < TN; u++) {
                float z = out[u];
                out[u] = (fminf(z, 0.f) - log1pf(__expf(-fabsf(z)))) * (1.f/32.f);
            }
        }
        float* crow = C + (size_t)(m0 + rid*8 + i) * N + n0 + cid*TN;
        if constexpr (TN == 8) {
            *reinterpret_cast<float4*>(crow)     = make_float4(out[0],out[1],out[2],out[3]);
            *reinterpret_cast<float4*>(crow + 4) = make_float4(out[4],out[5],out[6],out[7]);
        } else {
            *reinterpret_cast<float2*>(crow) = make_float2(out[0], out[1]);
        }
    }
}

// ---------------------------------------------------------------------------
// Chunked GLA v3 with fused gate. One block per (sequence n, head h).
// o = (intra + inter attention) -> RMS-norm(Dv) * gn * silu(r) -> og.
// ---------------------------------------------------------------------------
__device__ __forceinline__ int swzQ(int t, int d) { return (d + ((t & 3)  << 2)) & 63; }
__device__ __forceinline__ int swzK(int s, int d) { return (d + (s & 28)) & 63; }

__global__ void __launch_bounds__(256)
gla_kernel(const float* __restrict__ qkvr, const float* __restrict__ gkb,
           const float* __restrict__ gnp, float* __restrict__ og,
           int L, int nc)
{
    const int n   = blockIdx.x >> 2;
    const int h   = blockIdx.x & 3;
    const int tid = threadIdx.x;

    __shared__ __align__(16) float S[64][64];
    __shared__ __align__(16) float Qs[32][64];
    __shared__ __align__(16) float Ks[32][64];
    __shared__ __align__(16) float Vs[32][64];
    __shared__ __align__(16) float U[32][64];   // gate cumsum, then Amat

    for (int i = tid; i < 64*64; i += 256) (&S[0][0])[i] = 0.f;
    __syncthreads();

    const int glk0 = (tid >> 4) * 4;
    float glr[4];

    for (int c = 0; c < nc; c++) {
        const int lbase = c * 32;

        // ---- load gk chunk into U
        #pragma unroll
        for (int r = 0; r < 2; r++) {
            int i  = tid + r*256;
            int t  = i >> 4, d4 = (i & 15) * 4;
            int l  = lbase + t;
            float4 gv = make_float4(0.f, 0.f, 0.f, 0.f);
            if (l < L)
                gv = *reinterpret_cast<const float4*>(&gkb[((size_t)(n*L + l))*256 + h*64 + d4]);
            *reinterpret_cast<float4*>(&U[t][d4]) = gv;
        }
        __syncthreads();
        // ---- cumsum along t (per d)
        if (tid < 64) {
            float s = 0.f;
            #pragma unroll
            for (int t = 0; t < 32; t++) { s += U[t][tid]; U[t][tid] = s; }
        }
        __syncthreads();
        // ---- load q,k (scaled by exp(+-gc)) and v
        #pragma unroll
        for (int r = 0; r < 2; r++) {
            int i  = tid + r*256;
            int t  = i >> 4, d4 = (i & 15) * 4;
            int l  = lbase + t;
            float4 qv = make_float4(0,0,0,0), kv = qv, vv = qv;
            if (l < L) {
                size_t base = ((size_t)(n*L + l))*1024 + h*64 + d4;
                qv = *reinterpret_cast<const float4*>(&qkvr[base]);
                kv = *reinterpret_cast<const float4*>(&qkvr[base + 256]);
                vv = *reinterpret_cast<const float4*>(&qkvr[base + 512]);
                float4 g = *reinterpret_cast<const float4*>(&U[t][d4]);
                qv.x *= __expf(g.x);  qv.y *= __expf(g.y);
                qv.z *= __expf(g.z);  qv.w *= __expf(g.w);
                kv.x *= __expf(-g.x); kv.y *= __expf(-g.y);
                kv.z *= __expf(-g.z); kv.w *= __expf(-g.w);
            }
            *reinterpret_cast<float4*>(&Qs[t][swzQ(t, d4)]) = qv;
            *reinterpret_cast<float4*>(&Ks[t][swzK(t, d4)]) = kv;
            *reinterpret_cast<float4*>(&Vs[t][d4]) = vv;
        }
        #pragma unroll
        for (int i = 0; i < 4; i++) glr[i] = U[31][glk0 + i];
        __syncthreads();

        // ---- A[t][s] = q_i[t].k_i[s], masked s<=t, into U (FFMA2 dot)
        {
            int t  = tid >> 3;
            int s0 = (tid & 7) * 4;
            ull a2[4] = {0ull, 0ull, 0ull, 0ull};
            #pragma unroll
            for (int d = 0; d < 64; d += 4) {
                ulonglong2 qp = *reinterpret_cast<const ulonglong2*>(&Qs[t][swzQ(t, d)]);
                #pragma unroll
                for (int i = 0; i < 4; i++) {
                    ulonglong2 kp = *reinterpret_cast<const ulonglong2*>(&Ks[s0+i][swzK(s0+i, d)]);
                    ffma2(a2[i], qp.x, kp.x);
                    ffma2(a2[i], qp.y, kp.y);
                }
            }
            #pragma unroll
            for (int i = 0; i < 4; i++) {
                float2 f = upk(a2[i]);
                U[t][s0+i] = (s0 + i <= t) ? (f.x + f.y) : 0.f;
            }
        }
        __syncthreads();

        // ---- o[t] = A[t,:] @ V + q_i[t] @ S, then fused RMS+gate -> og
        {
            int t   = tid >> 3;
            int dv0 = (tid & 7) * 8;
            ull acc2[4] = {0ull, 0ull, 0ull, 0ull};
            #pragma unroll 8
            for (int s = 0; s < 32; s++) {
                ull ap = pk2(U[t][s]);
                ulonglong2 v0 = *reinterpret_cast<const ulonglong2*>(&Vs[s][dv0]);
                ulonglong2 v1 = *reinterpret_cast<const ulonglong2*>(&Vs[s][dv0+4]);
                ffma2(acc2[0], ap, v0.x); ffma2(acc2[1], ap, v0.y);
                ffma2(acc2[2], ap, v1.x); ffma2(acc2[3], ap, v1.y);
            }
            #pragma unroll 8
            for (int dk = 0; dk < 64; dk++) {
                ull ap = pk2(Qs[t][swzQ(t, dk)]);
                ulonglong2 s0v = *reinterpret_cast<const ulonglong2*>(&S[dk][dv0]);
                ulonglong2 s1v = *reinterpret_cast<const ulonglong2*>(&S[dk][dv0+4]);
                ffma2(acc2[0], ap, s0v.x); ffma2(acc2[1], ap, s0v.y);
                ffma2(acc2[2], ap, s1v.x); ffma2(acc2[3], ap, s1v.y);
            }
            float o8[8];
            #pragma unroll
            for (int j = 0; j < 4; j++) {
                float2 f = upk(acc2[j]);
                o8[2*j] = f.x; o8[2*j+1] = f.y;
            }
            float ss = 0.f;
            #pragma unroll
            for (int j = 0; j < 8; j++) ss += o8[j]*o8[j];
            ss += __shfl_xor_sync(0xFFFFFFFFu, ss, 4, 8);
            ss += __shfl_xor_sync(0xFFFFFFFFu, ss, 2, 8);
            ss += __shfl_xor_sync(0xFFFFFFFFu, ss, 1, 8);
            float inv = rsqrtf(ss * (1.f/64.f) + 1e-5f);
            int l = lbase + t;
            if (l < L) {
                size_t rb = ((size_t)(n*L + l))*1024 + 768 + h*64 + dv0;
                float4 r0 = *reinterpret_cast<const float4*>(&qkvr[rb]);
                float4 r1 = *reinterpret_cast<const float4*>(&qkvr[rb + 4]);
                float4 g0 = *reinterpret_cast<const float4*>(&gnp[h*64 + dv0]);
                float4 g1 = *reinterpret_cast<const float4*>(&gnp[h*64 + dv0 + 4]);
                float rr[8] = {r0.x,r0.y,r0.z,r0.w,r1.x,r1.y,r1.z,r1.w};
                float gg[8] = {g0.x,g0.y,g0.z,g0.w,g1.x,g1.y,g1.z,g1.w};
                float res[8];
                #pragma unroll
                for (int j = 0; j < 8; j++) {
                    float sil = rr[j] / (1.f + __expf(-rr[j]));
                    res[j] = o8[j] * inv * gg[j] * sil;
                }
                float* op = og + ((size_t)(n*L + l))*256 + h*64 + dv0;
                *reinterpret_cast<float4*>(op)     = make_float4(res[0],res[1],res[2],res[3]);
                *reinterpret_cast<float4*>(op + 4) = make_float4(res[4],res[5],res[6],res[7]);
            }
        }
        __syncthreads();

        // ---- S = exp(gl[dk]) * (S + k_i^T V)
        {
            int dk0 = glk0;
            int dv0 = (tid & 15) * 4;
            ull acc2[4][2] = {{0ull,0ull},{0ull,0ull},{0ull,0ull},{0ull,0ull}};
            #pragma unroll 8
            for (int s = 0; s < 32; s++) {
                float4 k4 = *reinterpret_cast<const float4*>(&Ks[s][swzK(s, dk0)]);
                ulonglong2 vp = *reinterpret_cast<const ulonglong2*>(&Vs[s][dv0]);
                float kk[4] = {k4.x, k4.y, k4.z, k4.w};
                #pragma unroll
                for (int i = 0; i < 4; i++) {
                    ull kp = pk2(kk[i]);
                    ffma2(acc2[i][0], kp, vp.x);
                    ffma2(acc2[i][1], kp, vp.y);
                }
            }
            #pragma unroll
            for (int i = 0; i < 4; i++) {
                float e = __expf(glr[i]);
                float2 f0 = upk(acc2[i][0]);
                float2 f1 = upk(acc2[i][1]);
                float4 sv = *reinterpret_cast<float4*>(&S[dk0+i][dv0]);
                sv.x = e*(sv.x + f0.x);
                sv.y = e*(sv.y + f0.y);
                sv.z = e*(sv.z + f1.x);
                sv.w = e*(sv.w + f1.y);
                *reinterpret_cast<float4*>(&S[dk0+i][dv0]) = sv;
            }
        }
        __syncthreads();
    }
}

// ---------------------------------------------------------------------------
// Deconv combine + residual. d01[m][2c+j] holds og @ (Wo @ ctw_flat).
// ---------------------------------------------------------------------------
__global__ void combine_kernel(const float* __restrict__ d01,
                               const float* __restrict__ ctb, const float* __restrict__ resid,
                               float* __restrict__ out, int pass)
{
    int idx = blockIdx.x * blockDim.x + threadIdx.x;
    if (idx >= ELEMS) return;
    int q = idx & 127;
    int t = (idx >> 7) & 255;
    int c = (idx >> 15) & 63;
    int b = idx >> 21;
    float acc = resid[idx] + ctb[c];
    if (pass == 0) {
        int n = b*256 + t;
        if (q < 127) acc += d01[((size_t)n*127 + q    )*128 + 2*c];
        if (q >= 1)  acc += d01[((size_t)n*127 + q - 1)*128 + 2*c + 1];
    } else {
        int n = b*128 + q;
        if (t < 255) acc += d01[((size_t)n*255 + t    )*128 + 2*c];
        if (t >= 1)  acc += d01[((size_t)n*255 + t - 1)*128 + 2*c + 1];
    }
    out[idx] = acc;
}

// ---------------------------------------------------------------------------
// Host side
// ---------------------------------------------------------------------------
static void run_pass(const float* input,
                     const float* gamma, const float* beta,
                     const float* Wq, const float* Wk, const float* Wv,
                     const float* Wg1, const float* Wg2, const float* Wr,
                     const float* gn, const float* Wo,
                     const float* ctw, const float* ctb,
                     const float* resid, float* out,
                     float* A, int pass)
{
    const int N   = pass == 0 ? 1024 : 512;
    const int L   = pass == 0 ? 127  : 255;
    const int Lf  = pass == 0 ? 128  : 256;
    const int nc  = pass == 0 ? 4    : 8;
    const int tok = N * L;                 // multiple of 128 in both passes

    float* f    = A + OF_F;
    float* qkvr = A + OF_QKVR;
    float* gk   = A + OF_GK;
    float* og   = A + OF_OG;
    float* t32  = A + OF_T32;
    float* d01  = A + OF_D01;
    float* un   = A + OF_UN;
    float* wp   = A + OF_WP;
    float* wf   = A + OF_WF;

    // 0. pack q/k/v/r weights; build Wf = Wo @ ctw_flat  [256,128]
    pack_kernel<<<128, 256>>>(Wq, Wk, Wv, Wr, wp);
    gemm2_kernel<0,128><<<dim3(2, 1), 256>>>(Wo, ctw, wf, 256, 128, 128);
    // 1. LayerNorm (channel dim) into pass layout
    ln_kernel<<<CDIV(4*256*128, 256), 256>>>(input, gamma, beta, un, pass);
    // 2. Unfold
    buildf_kernel<<<(unsigned)CDIV((size_t)N*64*L, 256), 256>>>(un, f, N, Lf, L);
    // 3. fused q|k|v|r projection
    gemm2_kernel<0,128><<<dim3(tok/128, 8), 256>>>(f, wp, qkvr, tok, 1024, 128);
    // 4. gk = log_sigmoid(f @ Wg1 @ Wg2) / 32
    gemm2_kernel<0,32><<<dim3(tok/128, 1), 256>>>(f, Wg1, t32, tok, 32, 128);
    gemm2_kernel<2,128><<<dim3(tok/128, 2), 256>>>(t32, Wg2, gk, tok, 256, 32);
    // 5. Chunked GLA with fused RMS-norm + gn + silu(r) gate
    gla_kernel<<<N*4, 256>>>(qkvr, gk, gn, og, L, nc);
    // 6. Output projection + deconv in ONE GEMM: d01 = og @ Wf
    gemm2_kernel<0,128><<<dim3(tok/128, 1), 256>>>(og, wf, d01, tok, 128, 256);
    // 7. Shift-combine + bias + residual
    combine_kernel<<<CDIV(ELEMS, 256), 256>>>(d01, ctb, resid, out, pass);
}

extern "C" void kernel_launch(void* const* d_in, const int* in_sizes, int n_in,
                              void* d_out, int out_size)
{
    const float* x = (const float*)d_in[0];
    auto P = [&](int i) { return (const float*)d_in[i]; };

    float* arena = nullptr;
    cudaGetSymbolAddress((void**)&arena, g_arena);
    float* y4 = arena + OF_Y4;

    // Pass 1 (intra): along Q.  params d_in[2..13]
    run_pass(x,
             P(2), P(3), P(4), P(5), P(6), P(7), P(8), P(9), P(10), P(11), P(12), P(13),
             x, y4, arena, 0);

    // Pass 2 (inter): along T.  params d_in[14..25]
    run_pass(y4,
             P(14), P(15), P(16), P(17), P(18), P(19), P(20), P(21), P(22), P(23), P(24), P(25),
             y4, (float*)d_out, arena, 1);
}

// round 5
// speedup vs baseline: 1.7945x; 1.1653x over previous
#include <cuda_runtime.h>
#include <cuda_bf16.h>
#include <math.h>
#include <stdint.h>

#define CDIV(a,b) (((a)+(b)-1)/(b))

typedef unsigned long long ull;

// ---- packed f32x2 helpers (sm_103a FFMA2 path) ------------------------------
__device__ __forceinline__ ull pk2(float x) {
    ull r; asm("mov.b64 %0, {%1, %1};" : "=l"(r) : "f"(x)); return r;
}
__device__ __forceinline__ void ffma2(ull& c, ull a, ull b) {
    asm("fma.rn.f32x2 %0, %1, %2, %0;" : "+l"(c) : "l"(a), "l"(b));
}
__device__ __forceinline__ float2 upk(ull v) {
    float2 f; asm("mov.b64 {%0, %1}, %2;" : "=f"(f.x), "=f"(f.y) : "l"(v)); return f;
}

constexpr int MAXTOK = 130560;     // max(1024*127, 512*255)
constexpr int ELEMS  = 4*64*256*128;

// ---------------------------------------------------------------------------
// Scratch arena (static device memory; no runtime allocation)
// ---------------------------------------------------------------------------
constexpr size_t OF_F    = 0;                               // f    : MAXTOK*128
constexpr size_t OF_QKVR = OF_F    + (size_t)MAXTOK*128;    // qkvr : MAXTOK*1024
constexpr size_t OF_GK   = OF_QKVR + (size_t)MAXTOK*1024;   // gk   : MAXTOK*256
constexpr size_t OF_OG   = OF_GK   + (size_t)MAXTOK*256;    // og   : MAXTOK*256
constexpr size_t OF_T32  = OF_OG   + (size_t)MAXTOK*256;    // t32  : MAXTOK*32
constexpr size_t OF_D01  = OF_T32  + (size_t)MAXTOK*32;     // d01  : MAXTOK*128
constexpr size_t OF_UN   = OF_D01  + (size_t)MAXTOK*128;    // un   : ELEMS
constexpr size_t OF_Y4   = OF_UN   + (size_t)ELEMS;         // y4   : ELEMS
constexpr size_t OF_WF   = OF_Y4   + (size_t)ELEMS;         // wf   : 256*128
constexpr size_t ARENA_TOTAL = OF_WF + (size_t)256*128;

__device__ __align__(128) float g_arena[ARENA_TOTAL];

// bf16 split weights (transposed to [N][K])
__device__ __align__(128) __nv_bfloat16 g_wpT_h[1024*128];
__device__ __align__(128) __nv_bfloat16 g_wpT_l[1024*128];
__device__ __align__(128) __nv_bfloat16 g_wg2T_h[256*32];
__device__ __align__(128) __nv_bfloat16 g_wg2T_l[256*32];
__device__ __align__(128) __nv_bfloat16 g_wfT_h[128*256];
__device__ __align__(128) __nv_bfloat16 g_wfT_l[128*256];

// ---------------------------------------------------------------------------
// bf16 hi/lo split
// ---------------------------------------------------------------------------
__device__ __forceinline__ void bsplit(float x, __nv_bfloat16& h, __nv_bfloat16& l) {
    h = __float2bfloat16_rn(x);
    l = __float2bfloat16_rn(x - __bfloat162float(h));
}

// ---------------------------------------------------------------------------
// Weight prep: transpose + split.
// ---------------------------------------------------------------------------
__global__ void packT_kernel(const float* __restrict__ Wq, const float* __restrict__ Wk,
                             const float* __restrict__ Wv, const float* __restrict__ Wr,
                             __nv_bfloat16* __restrict__ th, __nv_bfloat16* __restrict__ tl)
{
    int idx = blockIdx.x * 256 + threadIdx.x;   // 1024*128
    if (idx >= 1024*128) return;
    int n = idx >> 7, k = idx & 127;
    int grp = n >> 8, nn = n & 255;
    const float* W = (grp == 0) ? Wq : (grp == 1) ? Wk : (grp == 2) ? Wv : Wr;
    float x = W[k*256 + nn] * ((grp == 0) ? 0.125f : 1.f);
    __nv_bfloat16 h, l; bsplit(x, h, l);
    th[idx] = h; tl[idx] = l;
}

__global__ void transT_kernel(const float* __restrict__ W,
                              __nv_bfloat16* __restrict__ th, __nv_bfloat16* __restrict__ tl,
                              int K, int N)
{
    int idx = blockIdx.x * 256 + threadIdx.x;
    if (idx >= N*K) return;
    int n = idx / K, k = idx % K;
    __nv_bfloat16 h, l; bsplit(W[k*N + n], h, l);
    th[idx] = h; tl[idx] = l;
}

// ---------------------------------------------------------------------------
// HMMA plumbing (mma.sync + ldmatrix -- baseline sm_80+ PTX, no arch suffix)
// ---------------------------------------------------------------------------
__device__ __forceinline__ uint32_t s2u(const void* p) {
    uint32_t a;
    asm("{ .reg .u64 t; cvta.to.shared.u64 t, %1; cvt.u32.u64 %0, t; }" : "=r"(a) : "l"(p));
    return a;
}
#define SWZ(x) ((x) ^ (((x) >> 3) & 0x70))

__device__ __forceinline__ void ldm4(uint32_t* r, uint32_t addr) {
    asm volatile("ldmatrix.sync.aligned.m8n8.x4.shared.b16 {%0,%1,%2,%3}, [%4];"
        : "=r"(r[0]), "=r"(r[1]), "=r"(r[2]), "=r"(r[3]) : "r"(addr));
}
__device__ __forceinline__ void mma16816(float* d, const uint32_t* a, uint32_t b0, uint32_t b1) {
    asm volatile("mma.sync.aligned.m16n8k16.row.col.f32.bf16.bf16.f32 "
        "{%0,%1,%2,%3}, {%4,%5,%6,%7}, {%8,%9}, {%0,%1,%2,%3};"
        : "+f"(d[0]), "+f"(d[1]), "+f"(d[2]), "+f"(d[3])
        : "r"(a[0]), "r"(a[1]), "r"(a[2]), "r"(a[3]), "r"(b0), "r"(b1));
}

// ---------------------------------------------------------------------------
// HMMA split-bf16 GEMM: C[M,N] = A[M,K] @ Bt[N,K]^T   (fp32 in/out)
// CTA tile 128x128, 8 warps (4x2), warp tile 32x64, K chunked by 64.
// D = Ah*Bh + Ah*Bl + Al*Bh.  EPI: 0=none, 2=log_sigmoid(z)/32
// Requirements: M%128==0, N%128==0.
// ---------------------------------------------------------------------------
template<int EPI>
__global__ void __launch_bounds__(256, 2)
hmma_gemm(const float* __restrict__ A,
          const __nv_bfloat16* __restrict__ Bh, const __nv_bfloat16* __restrict__ Bl,
          float* __restrict__ C, int M, int N, int K)
{
    extern __shared__ char smem[];
    const uint32_t sb = s2u(smem);
    constexpr int AH = 0;
    constexpr int AL = 16384;
    constexpr int BH = 32768;
    constexpr int BL = 49152;

    const int tid  = threadIdx.x;
    const int m0   = blockIdx.x * 128;
    const int n0   = blockIdx.y * 128;
    const int lane = tid & 31;
    const int w    = tid >> 5;
    const int m0w  = (w & 3) * 32;
    const int n0w  = (w >> 2) * 64;
    const int lrow = lane & 15;
    const int lk8  = (lane >> 4) << 3;

    float d[2][8][4];
    #pragma unroll
    for (int mt = 0; mt < 2; mt++)
        #pragma unroll
        for (int nt = 0; nt < 8; nt++)
            #pragma unroll
            for (int u = 0; u < 4; u++) d[mt][nt][u] = 0.f;

    const int nchunks = (K + 63) >> 6;
    for (int ch = 0; ch < nchunks; ch++) {
        const int kc0 = ch << 6;
        const int Kc  = (K - kc0 < 64) ? (K - kc0) : 64;

        // ---- A tile: 128 x Kc fp32 -> bf16 hi/lo, swizzled 128B rows
        #pragma unroll
        for (int it = 0; it < 8; it++) {
            int i = tid + it*256;
            int r = i >> 4, c4 = (i & 15) * 4;
            ull hp = 0, lp = 0;
            if (c4 < Kc) {
                float4 v = *reinterpret_cast<const float4*>(&A[(size_t)(m0 + r)*K + kc0 + c4]);
                float f[4] = {v.x, v.y, v.z, v.w};
                uint16_t hu[4], lu[4];
                #pragma unroll
                for (int j = 0; j < 4; j++) {
                    __nv_bfloat16 h, l; bsplit(f[j], h, l);
                    hu[j] = __bfloat16_as_ushort(h);
                    lu[j] = __bfloat16_as_ushort(l);
                }
                hp = (ull)hu[0] | ((ull)hu[1] << 16) | ((ull)hu[2] << 32) | ((ull)hu[3] << 48);
                lp = (ull)lu[0] | ((ull)lu[1] << 16) | ((ull)lu[2] << 32) | ((ull)lu[3] << 48);
            }
            int off = SWZ(r*128 + c4*2);
            *reinterpret_cast<ull*>(smem + AH + off) = hp;
            *reinterpret_cast<ull*>(smem + AL + off) = lp;
        }
        // ---- B tile: 128 x Kc bf16 hi/lo (pre-split), swizzled
        #pragma unroll
        for (int it = 0; it < 4; it++) {
            int i = tid + it*256;
            int r = i >> 3, c8 = (i & 7) * 8;
            uint4 hv = make_uint4(0,0,0,0), lv = hv;
            if (c8 < Kc) {
                hv = *reinterpret_cast<const uint4*>(&Bh[(size_t)(n0 + r)*K + kc0 + c8]);
                lv = *reinterpret_cast<const uint4*>(&Bl[(size_t)(n0 + r)*K + kc0 + c8]);
            }
            int off = SWZ(r*128 + c8*2);
            *reinterpret_cast<uint4*>(smem + BH + off) = hv;
            *reinterpret_cast<uint4*>(smem + BL + off) = lv;
        }
        __syncthreads();

        // ---- MMA: ksteps of 16
        const int ksteps = (Kc + 15) >> 4;
        for (int ks = 0; ks < ksteps; ks++) {
            const int kcol = ks*16 + lk8;
            uint32_t ah[2][4], al2[2][4], bb[4][4];
            #pragma unroll
            for (int mt = 0; mt < 2; mt++) {
                uint32_t off = SWZ((m0w + mt*16 + lrow)*128 + kcol*2);
                ldm4(ah[mt],  sb + AH + off);
                ldm4(al2[mt], sb + AL + off);
            }
            #pragma unroll
            for (int nt2 = 0; nt2 < 4; nt2++) {
                uint32_t off = SWZ((n0w + nt2*16 + lrow)*128 + kcol*2);
                ldm4(bb[nt2], sb + BH + off);
            }
            #pragma unroll
            for (int mt = 0; mt < 2; mt++)
                #pragma unroll
                for (int nt = 0; nt < 8; nt++) {
                    uint32_t b0 = (nt & 1) ? bb[nt>>1][1] : bb[nt>>1][0];
                    uint32_t b1 = (nt & 1) ? bb[nt>>1][3] : bb[nt>>1][2];
                    mma16816(d[mt][nt], ah[mt],  b0, b1);   // Ah*Bh
                    mma16816(d[mt][nt], al2[mt], b0, b1);   // Al*Bh
                }
            #pragma unroll
            for (int nt2 = 0; nt2 < 4; nt2++) {
                uint32_t off = SWZ((n0w + nt2*16 + lrow)*128 + kcol*2);
                ldm4(bb[nt2], sb + BL + off);
            }
            #pragma unroll
            for (int mt = 0; mt < 2; mt++)
                #pragma unroll
                for (int nt = 0; nt < 8; nt++) {
                    uint32_t b0 = (nt & 1) ? bb[nt>>1][1] : bb[nt>>1][0];
                    uint32_t b1 = (nt & 1) ? bb[nt>>1][3] : bb[nt>>1][2];
                    mma16816(d[mt][nt], ah[mt], b0, b1);    // Ah*Bl
                }
        }
        __syncthreads();
    }

    // ---- epilogue: fragment (r = lane>>2, c = (lane&3)*2), rows +8 for d2/d3
    const int er = lane >> 2;
    const int ec = (lane & 3) * 2;
    #pragma unroll
    for (int mt = 0; mt < 2; mt++) {
        #pragma unroll
        for (int nt = 0; nt < 8; nt++) {
            float v[4] = {d[mt][nt][0], d[mt][nt][1], d[mt][nt][2], d[mt][nt][3]};
            if (EPI == 2) {
                #pragma unroll
                for (int u = 0; u < 4; u++)
                    v[u] = (fminf(v[u], 0.f) - log1pf(__expf(-fabsf(v[u])))) * (1.f/32.f);
            }
            size_t m = (size_t)(m0 + m0w + mt*16 + er);
            int    n = n0 + n0w + nt*8 + ec;
            *reinterpret_cast<float2*>(&C[m*N + n])        = make_float2(v[0], v[1]);
            *reinterpret_cast<float2*>(&C[(m + 8)*N + n])  = make_float2(v[2], v[3]);
        }
    }
}

// ---------------------------------------------------------------------------
// LayerNorm over channel dim C=64, written in pass layout.
// ---------------------------------------------------------------------------
__global__ void ln_kernel(const float* __restrict__ x,
                          const float* __restrict__ gamma,
                          const float* __restrict__ beta,
                          float* __restrict__ un, int pass)
{
    int idx = blockIdx.x * blockDim.x + threadIdx.x;
    if (idx >= 4*256*128) return;
    int q = idx & 127;
    int t = (idx >> 7) & 255;
    int b = idx >> 15;
    size_t base = ((size_t)b*64*256 + t)*128 + q;
    float sum = 0.f, sq = 0.f;
    #pragma unroll 8
    for (int c = 0; c < 64; c++) {
        float v = x[base + (size_t)c*32768];
        sum += v; sq += v*v;
    }
    float mu  = sum * (1.f/64.f);
    float var = sq  * (1.f/64.f) - mu*mu;
    float inv = rsqrtf(var + 1e-5f);
    #pragma unroll 8
    for (int c = 0; c < 64; c++) {
        float v = (x[base + (size_t)c*32768] - mu) * inv * gamma[c] + beta[c];
        size_t o;
        if (pass == 0) o = (((size_t)(b*256 + t))*64 + c)*128 + q;
        else           o = (((size_t)(b*128 + q))*64 + c)*256 + t;
        un[o] = v;
    }
}

// ---------------------------------------------------------------------------
// Unfold: f[n, l, 2c+k] = un[n, c, l+k]
// ---------------------------------------------------------------------------
__global__ void buildf_kernel(const float* __restrict__ un, float* __restrict__ f,
                              int Nn, int Lf, int L)
{
    size_t idx = (size_t)blockIdx.x * blockDim.x + threadIdx.x;
    size_t total = (size_t)Nn * 64 * L;
    if (idx >= total) return;
    int l = (int)(idx % L);
    int c = (int)((idx / L) % 64);
    int n = (int)(idx / ((size_t)L * 64));
    const float* up = un + ((size_t)n*64 + c)*Lf + l;
    float2 v = make_float2(up[0], up[1]);
    *reinterpret_cast<float2*>(f + ((size_t)n*L + l)*128 + 2*c) = v;
}

// ---------------------------------------------------------------------------
// FFMA2 SGEMM (small shapes): C[M,N] = A[M,K] @ B[K,N]
// ---------------------------------------------------------------------------
template<int EPI, int BN>
__global__ void __launch_bounds__(256, 2)
gemm2_kernel(const float* __restrict__ A, const float* __restrict__ B,
             float* __restrict__ C, int M, int N, int K)
{
    constexpr int TN  = BN / 16;
    constexpr int TN2 = TN / 2;
    __shared__ __align__(16) float As[2][16][132];
    __shared__ __align__(16) float Bs[2][16][BN + 4];

    const int tid = threadIdx.x;
    const int m0  = blockIdx.x * 128;
    const int n0  = blockIdx.y * BN;
    const int rid = tid >> 4;
    const int cid = tid & 15;

    const int ar0 = tid >> 2;
    const int ar1 = ar0 + 64;
    const int ac0 = (tid & 3) * 4;
    const int bkk = tid >> 4;
    const int bnn = (tid & 15) * TN;

    const float* Ap0 = A + (size_t)(m0 + ar0)*K + ac0;
    const float* Ap1 = A + (size_t)(m0 + ar1)*K + ac0;
    const float* Bp  = B + (size_t)bkk*N + n0 + bnn;

    float4 va0, va1, vb0, vb1; float2 vb2;

    va0 = *reinterpret_cast<const float4*>(Ap0);
    va1 = *reinterpret_cast<const float4*>(Ap1);
    if constexpr (TN == 8) {
        vb0 = *reinterpret_cast<const float4*>(Bp);
        vb1 = *reinterpret_cast<const float4*>(Bp + 4);
    } else {
        vb2 = *reinterpret_cast<const float2*>(Bp);
    }
    As[0][ac0+0][ar0] = va0.x; As[0][ac0+1][ar0] = va0.y;
    As[0][ac0+2][ar0] = va0.z; As[0][ac0+3][ar0] = va0.w;
    As[0][ac0+0][ar1] = va1.x; As[0][ac0+1][ar1] = va1.y;
    As[0][ac0+2][ar1] = va1.z; As[0][ac0+3][ar1] = va1.w;
    if constexpr (TN == 8) {
        *reinterpret_cast<float4*>(&Bs[0][bkk][bnn]) = vb0;
        *reinterpret_cast<float4*>(&Bs[0][bkk][bnn + 4]) = vb1;
    } else {
        *reinterpret_cast<float2*>(&Bs[0][bkk][bnn]) = vb2;
    }
    __syncthreads();

    ull acc[8][TN2];
    #pragma unroll
    for (int i = 0; i < 8; i++)
        #pragma unroll
        for (int j = 0; j < TN2; j++) acc[i][j] = 0ull;

    int buf = 0;
    for (int k0 = 0; k0 < K; k0 += 16) {
        const bool nxt = (k0 + 16) < K;
        if (nxt) {
            const int kn = k0 + 16;
            va0 = *reinterpret_cast<const float4*>(Ap0 + kn);
            va1 = *reinterpret_cast<const float4*>(Ap1 + kn);
            if constexpr (TN == 8) {
                vb0 = *reinterpret_cast<const float4*>(Bp + (size_t)kn*N);
                vb1 = *reinterpret_cast<const float4*>(Bp + (size_t)kn*N + 4);
            } else {
                vb2 = *reinterpret_cast<const float2*>(Bp + (size_t)kn*N);
            }
        }
        #pragma unroll
        for (int kk = 0; kk < 16; kk++) {
            float4 a0 = *reinterpret_cast<const float4*>(&As[buf][kk][rid*8]);
            float4 a1 = *reinterpret_cast<const float4*>(&As[buf][kk][rid*8+4]);
            float av[8] = {a0.x,a0.y,a0.z,a0.w,a1.x,a1.y,a1.z,a1.w};
            ull ap[8];
            #pragma unroll
            for (int i = 0; i < 8; i++) ap[i] = pk2(av[i]);
            ull bp[TN2];
            if constexpr (TN == 8) {
                ulonglong2 b01 = *reinterpret_cast<const ulonglong2*>(&Bs[buf][kk][cid*8]);
                ulonglong2 b23 = *reinterpret_cast<const ulonglong2*>(&Bs[buf][kk][cid*8 + 4]);
                bp[0] = b01.x; bp[1] = b01.y; bp[2] = b23.x; bp[3] = b23.y;
            } else {
                bp[0] = *reinterpret_cast<const ull*>(&Bs[buf][kk][cid*2]);
            }
            #pragma unroll
            for (int i = 0; i < 8; i++)
                #pragma unroll
                for (int j = 0; j < TN2; j++)
                    ffma2(acc[i][j], ap[i], bp[j]);
        }
        if (nxt) {
            const int nb = buf ^ 1;
            As[nb][ac0+0][ar0] = va0.x; As[nb][ac0+1][ar0] = va0.y;
            As[nb][ac0+2][ar0] = va0.z; As[nb][ac0+3][ar0] = va0.w;
            As[nb][ac0+0][ar1] = va1.x; As[nb][ac0+1][ar1] = va1.y;
            As[nb][ac0+2][ar1] = va1.z; As[nb][ac0+3][ar1] = va1.w;
            if constexpr (TN == 8) {
                *reinterpret_cast<float4*>(&Bs[nb][bkk][bnn]) = vb0;
                *reinterpret_cast<float4*>(&Bs[nb][bkk][bnn + 4]) = vb1;
            } else {
                *reinterpret_cast<float2*>(&Bs[nb][bkk][bnn]) = vb2;
            }
        }
        __syncthreads();
        buf ^= 1;
    }

    #pragma unroll
    for (int i = 0; i < 8; i++) {
        float out[TN];
        #pragma unroll
        for (int j = 0; j < TN2; j++) {
            float2 f = upk(acc[i][j]);
            out[2*j] = f.x; out[2*j+1] = f.y;
        }
        if (EPI == 2) {
            #pragma unroll
            for (int u = 0; u < TN; u++) {
                float z = out[u];
                out[u] = (fminf(z, 0.f) - log1pf(__expf(-fabsf(z)))) * (1.f/32.f);
            }
        }
        float* crow = C + (size_t)(m0 + rid*8 + i) * N + n0 + cid*TN;
        if constexpr (TN == 8) {
            *reinterpret_cast<float4*>(crow)     = make_float4(out[0],out[1],out[2],out[3]);
            *reinterpret_cast<float4*>(crow + 4) = make_float4(out[4],out[5],out[6],out[7]);
        } else {
            *reinterpret_cast<float2*>(crow) = make_float2(out[0], out[1]);
        }
    }
}

// ---------------------------------------------------------------------------
// Chunked GLA with fused gate (unchanged from round 3)
// ---------------------------------------------------------------------------
__device__ __forceinline__ int swzQ(int t, int d) { return (d + ((t & 3)  << 2)) & 63; }
__device__ __forceinline__ int swzK(int s, int d) { return (d + (s & 28)) & 63; }

__global__ void __launch_bounds__(256)
gla_kernel(const float* __restrict__ qkvr, const float* __restrict__ gkb,
           const float* __restrict__ gnp, float* __restrict__ og,
           int L, int nc)
{
    const int n   = blockIdx.x >> 2;
    const int h   = blockIdx.x & 3;
    const int tid = threadIdx.x;

    __shared__ __align__(16) float S[64][64];
    __shared__ __align__(16) float Qs[32][64];
    __shared__ __align__(16) float Ks[32][64];
    __shared__ __align__(16) float Vs[32][64];
    __shared__ __align__(16) float U[32][64];

    for (int i = tid; i < 64*64; i += 256) (&S[0][0])[i] = 0.f;
    __syncthreads();

    const int glk0 = (tid >> 4) * 4;
    float glr[4];

    for (int c = 0; c < nc; c++) {
        const int lbase = c * 32;

        #pragma unroll
        for (int r = 0; r < 2; r++) {
            int i  = tid + r*256;
            int t  = i >> 4, d4 = (i & 15) * 4;
            int l  = lbase + t;
            float4 gv = make_float4(0.f, 0.f, 0.f, 0.f);
            if (l < L)
                gv = *reinterpret_cast<const float4*>(&gkb[((size_t)(n*L + l))*256 + h*64 + d4]);
            *reinterpret_cast<float4*>(&U[t][d4]) = gv;
        }
        __syncthreads();
        if (tid < 64) {
            float s = 0.f;
            #pragma unroll
            for (int t = 0; t < 32; t++) { s += U[t][tid]; U[t][tid] = s; }
        }
        __syncthreads();
        #pragma unroll
        for (int r = 0; r < 2; r++) {
            int i  = tid + r*256;
            int t  = i >> 4, d4 = (i & 15) * 4;
            int l  = lbase + t;
            float4 qv = make_float4(0,0,0,0), kv = qv, vv = qv;
            if (l < L) {
                size_t base = ((size_t)(n*L + l))*1024 + h*64 + d4;
                qv = *reinterpret_cast<const float4*>(&qkvr[base]);
                kv = *reinterpret_cast<const float4*>(&qkvr[base + 256]);
                vv = *reinterpret_cast<const float4*>(&qkvr[base + 512]);
                float4 g = *reinterpret_cast<const float4*>(&U[t][d4]);
                qv.x *= __expf(g.x);  qv.y *= __expf(g.y);
                qv.z *= __expf(g.z);  qv.w *= __expf(g.w);
                kv.x *= __expf(-g.x); kv.y *= __expf(-g.y);
                kv.z *= __expf(-g.z); kv.w *= __expf(-g.w);
            }
            *reinterpret_cast<float4*>(&Qs[t][swzQ(t, d4)]) = qv;
            *reinterpret_cast<float4*>(&Ks[t][swzK(t, d4)]) = kv;
            *reinterpret_cast<float4*>(&Vs[t][d4]) = vv;
        }
        #pragma unroll
        for (int i = 0; i < 4; i++) glr[i] = U[31][glk0 + i];
        __syncthreads();

        {
            int t  = tid >> 3;
            int s0 = (tid & 7) * 4;
            ull a2[4] = {0ull, 0ull, 0ull, 0ull};
            #pragma unroll
            for (int d = 0; d < 64; d += 4) {
                ulonglong2 qp = *reinterpret_cast<const ulonglong2*>(&Qs[t][swzQ(t, d)]);
                #pragma unroll
                for (int i = 0; i < 4; i++) {
                    ulonglong2 kp = *reinterpret_cast<const ulonglong2*>(&Ks[s0+i][swzK(s0+i, d)]);
                    ffma2(a2[i], qp.x, kp.x);
                    ffma2(a2[i], qp.y, kp.y);
                }
            }
            #pragma unroll
            for (int i = 0; i < 4; i++) {
                float2 f = upk(a2[i]);
                U[t][s0+i] = (s0 + i <= t) ? (f.x + f.y) : 0.f;
            }
        }
        __syncthreads();

        {
            int t   = tid >> 3;
            int dv0 = (tid & 7) * 8;
            ull acc2[4] = {0ull, 0ull, 0ull, 0ull};
            #pragma unroll 8
            for (int s = 0; s < 32; s++) {
                ull ap = pk2(U[t][s]);
                ulonglong2 v0 = *reinterpret_cast<const ulonglong2*>(&Vs[s][dv0]);
                ulonglong2 v1 = *reinterpret_cast<const ulonglong2*>(&Vs[s][dv0+4]);
                ffma2(acc2[0], ap, v0.x); ffma2(acc2[1], ap, v0.y);
                ffma2(acc2[2], ap, v1.x); ffma2(acc2[3], ap, v1.y);
            }
            #pragma unroll 8
            for (int dk = 0; dk < 64; dk++) {
                ull ap = pk2(Qs[t][swzQ(t, dk)]);
                ulonglong2 s0v = *reinterpret_cast<const ulonglong2*>(&S[dk][dv0]);
                ulonglong2 s1v = *reinterpret_cast<const ulonglong2*>(&S[dk][dv0+4]);
                ffma2(acc2[0], ap, s0v.x); ffma2(acc2[1], ap, s0v.y);
                ffma2(acc2[2], ap, s1v.x); ffma2(acc2[3], ap, s1v.y);
            }
            float o8[8];
            #pragma unroll
            for (int j = 0; j < 4; j++) {
                float2 f = upk(acc2[j]);
                o8[2*j] = f.x; o8[2*j+1] = f.y;
            }
            float ss = 0.f;
            #pragma unroll
            for (int j = 0; j < 8; j++) ss += o8[j]*o8[j];
            ss += __shfl_xor_sync(0xFFFFFFFFu, ss, 4, 8);
            ss += __shfl_xor_sync(0xFFFFFFFFu, ss, 2, 8);
            ss += __shfl_xor_sync(0xFFFFFFFFu, ss, 1, 8);
            float inv = rsqrtf(ss * (1.f/64.f) + 1e-5f);
            int l = lbase + t;
            if (l < L) {
                size_t rb = ((size_t)(n*L + l))*1024 + 768 + h*64 + dv0;
                float4 r0 = *reinterpret_cast<const float4*>(&qkvr[rb]);
                float4 r1 = *reinterpret_cast<const float4*>(&qkvr[rb + 4]);
                float4 g0 = *reinterpret_cast<const float4*>(&gnp[h*64 + dv0]);
                float4 g1 = *reinterpret_cast<const float4*>(&gnp[h*64 + dv0 + 4]);
                float rr[8] = {r0.x,r0.y,r0.z,r0.w,r1.x,r1.y,r1.z,r1.w};
                float gg[8] = {g0.x,g0.y,g0.z,g0.w,g1.x,g1.y,g1.z,g1.w};
                float res[8];
                #pragma unroll
                for (int j = 0; j < 8; j++) {
                    float sil = rr[j] / (1.f + __expf(-rr[j]));
                    res[j] = o8[j] * inv * gg[j] * sil;
                }
                float* op = og + ((size_t)(n*L + l))*256 + h*64 + dv0;
                *reinterpret_cast<float4*>(op)     = make_float4(res[0],res[1],res[2],res[3]);
                *reinterpret_cast<float4*>(op + 4) = make_float4(res[4],res[5],res[6],res[7]);
            }
        }
        __syncthreads();

        {
            int dk0 = glk0;
            int dv0 = (tid & 15) * 4;
            ull acc2[4][2] = {{0ull,0ull},{0ull,0ull},{0ull,0ull},{0ull,0ull}};
            #pragma unroll 8
            for (int s = 0; s < 32; s++) {
                float4 k4 = *reinterpret_cast<const float4*>(&Ks[s][swzK(s, dk0)]);
                ulonglong2 vp = *reinterpret_cast<const ulonglong2*>(&Vs[s][dv0]);
                float kk[4] = {k4.x, k4.y, k4.z, k4.w};
                #pragma unroll
                for (int i = 0; i < 4; i++) {
                    ull kp = pk2(kk[i]);
                    ffma2(acc2[i][0], kp, vp.x);
                    ffma2(acc2[i][1], kp, vp.y);
                }
            }
            #pragma unroll
            for (int i = 0; i < 4; i++) {
                float e = __expf(glr[i]);
                float2 f0 = upk(acc2[i][0]);
                float2 f1 = upk(acc2[i][1]);
                float4 sv = *reinterpret_cast<float4*>(&S[dk0+i][dv0]);
                sv.x = e*(sv.x + f0.x);
                sv.y = e*(sv.y + f0.y);
                sv.z = e*(sv.z + f1.x);
                sv.w = e*(sv.w + f1.y);
                *reinterpret_cast<float4*>(&S[dk0+i][dv0]) = sv;
            }
        }
        __syncthreads();
    }
}

// ---------------------------------------------------------------------------
// Deconv combine + residual.
// ---------------------------------------------------------------------------
__global__ void combine_kernel(const float* __restrict__ d01,
                               const float* __restrict__ ctb, const float* __restrict__ resid,
                               float* __restrict__ out, int pass)
{
    int idx = blockIdx.x * blockDim.x + threadIdx.x;
    if (idx >= ELEMS) return;
    int q = idx & 127;
    int t = (idx >> 7) & 255;
    int c = (idx >> 15) & 63;
    int b = idx >> 21;
    float acc = resid[idx] + ctb[c];
    if (pass == 0) {
        int n = b*256 + t;
        if (q < 127) acc += d01[((size_t)n*127 + q    )*128 + 2*c];
        if (q >= 1)  acc += d01[((size_t)n*127 + q - 1)*128 + 2*c + 1];
    } else {
        int n = b*128 + q;
        if (t < 255) acc += d01[((size_t)n*255 + t    )*128 + 2*c];
        if (t >= 1)  acc += d01[((size_t)n*255 + t - 1)*128 + 2*c + 1];
    }
    out[idx] = acc;
}

// ---------------------------------------------------------------------------
// Host side
// ---------------------------------------------------------------------------
struct WPtrs {
    __nv_bfloat16 *wpT_h, *wpT_l, *wg2T_h, *wg2T_l, *wfT_h, *wfT_l;
};

constexpr int HSM = 65536;   // hmma_gemm dynamic smem

static void run_pass(const float* input,
                     const float* gamma, const float* beta,
                     const float* Wq, const float* Wk, const float* Wv,
                     const float* Wg1, const float* Wg2, const float* Wr,
                     const float* gn, const float* Wo,
                     const float* ctw, const float* ctb,
                     const float* resid, float* out,
                     float* A, const WPtrs& W, int pass)
{
    const int N   = pass == 0 ? 1024 : 512;
    const int L   = pass == 0 ? 127  : 255;
    const int Lf  = pass == 0 ? 128  : 256;
    const int nc  = pass == 0 ? 4    : 8;
    const int tok = N * L;
    const int Mt  = tok / 128;

    float* f    = A + OF_F;
    float* qkvr = A + OF_QKVR;
    float* gk   = A + OF_GK;
    float* og   = A + OF_OG;
    float* t32  = A + OF_T32;
    float* d01  = A + OF_D01;
    float* un   = A + OF_UN;
    float* wf   = A + OF_WF;

    // 0. weight prep: transpose + bf16 split
    packT_kernel<<<512, 256>>>(Wq, Wk, Wv, Wr, W.wpT_h, W.wpT_l);
    transT_kernel<<<CDIV(256*32, 256), 256>>>(Wg2, W.wg2T_h, W.wg2T_l, 32, 256);
    gemm2_kernel<0,128><<<dim3(2, 1), 256>>>(Wo, ctw, wf, 256, 128, 128);
    transT_kernel<<<CDIV(128*256, 256), 256>>>(wf, W.wfT_h, W.wfT_l, 256, 128);
    // 1. LayerNorm into pass layout
    ln_kernel<<<CDIV(4*256*128, 256), 256>>>(input, gamma, beta, un, pass);
    // 2. Unfold
    buildf_kernel<<<(unsigned)CDIV((size_t)N*64*L, 256), 256>>>(un, f, N, Lf, L);
    // 3. fused q|k|v|r projection (HMMA split-bf16)
    hmma_gemm<0><<<dim3(Mt, 8), 256, HSM>>>(f, W.wpT_h, W.wpT_l, qkvr, tok, 1024, 128);
    // 4. gk = log_sigmoid(f @ Wg1 @ Wg2) / 32
    gemm2_kernel<0,32><<<dim3(Mt, 1), 256>>>(f, Wg1, t32, tok, 32, 128);
    hmma_gemm<2><<<dim3(Mt, 2), 256, HSM>>>(t32, W.wg2T_h, W.wg2T_l, gk, tok, 256, 32);
    // 5. Chunked GLA with fused RMS-norm + gn + silu(r) gate
    gla_kernel<<<N*4, 256>>>(qkvr, gk, gn, og, L, nc);
    // 6. Output projection + deconv in one GEMM: d01 = og @ Wf
    hmma_gemm<0><<<dim3(Mt, 1), 256, HSM>>>(og, W.wfT_h, W.wfT_l, d01, tok, 128, 256);
    // 7. Shift-combine + bias + residual
    combine_kernel<<<CDIV(ELEMS, 256), 256>>>(d01, ctb, resid, out, pass);
}

extern "C" void kernel_launch(void* const* d_in, const int* in_sizes, int n_in,
                              void* d_out, int out_size)
{
    const float* x = (const float*)d_in[0];
    auto P = [&](int i) { return (const float*)d_in[i]; };

    float* arena = nullptr;
    cudaGetSymbolAddress((void**)&arena, g_arena);
    float* y4 = arena + OF_Y4;

    WPtrs W;
    cudaGetSymbolAddress((void**)&W.wpT_h,  g_wpT_h);
    cudaGetSymbolAddress((void**)&W.wpT_l,  g_wpT_l);
    cudaGetSymbolAddress((void**)&W.wg2T_h, g_wg2T_h);
    cudaGetSymbolAddress((void**)&W.wg2T_l, g_wg2T_l);
    cudaGetSymbolAddress((void**)&W.wfT_h,  g_wfT_h);
    cudaGetSymbolAddress((void**)&W.wfT_l,  g_wfT_l);

    cudaFuncSetAttribute(hmma_gemm<0>, cudaFuncAttributeMaxDynamicSharedMemorySize, HSM);
    cudaFuncSetAttribute(hmma_gemm<2>, cudaFuncAttributeMaxDynamicSharedMemorySize, HSM);

    // Pass 1 (intra): along Q.  params d_in[2..13]
    run_pass(x,
             P(2), P(3), P(4), P(5), P(6), P(7), P(8), P(9), P(10), P(11), P(12), P(13),
             x, y4, arena, W, 0);

    // Pass 2 (inter): along T.  params d_in[14..25]
    run_pass(y4,
             P(14), P(15), P(16), P(17), P(18), P(19), P(20), P(21), P(22), P(23), P(24), P(25),
             y4, (float*)d_out, arena, W, 1);
}